// round 1
// baseline (speedup 1.0000x reference)
#include <cuda_runtime.h>
#include <math.h>

#define B_TOTAL 131072
#define SD 128
#define AD 32
#define XD 160
#define HDIM 256
#define ROWS 64           // rows per block
#define BK 32             // K tile
#define NTHREADS 256

// Precomputed measurement matrices: Re(M) where M = U^dag (Z0) U, per branch.
__device__ float d_M[2][256];

// ---------------------------------------------------------------------------
// Setup: build the fixed 16x16 Hermitian form for each branch's circuit.
// Thread j computes column j of U by simulating the fixed part of the circuit
// on basis state e_j; then M_ij = sum_k d_k conj(U[k,i]) U[k,j], d_k = +-1.
// ---------------------------------------------------------------------------
__global__ void setup_M_kernel(const float* __restrict__ qw1,
                               const float* __restrict__ qw2) {
    const int br = blockIdx.x;
    const int j  = threadIdx.x;
    const float* qw = br ? qw2 : qw1;
    __shared__ float Ur[16][16];
    __shared__ float Ui[16][16];

    if (j < 16) {
        float sr[16], si[16];
        #pragma unroll
        for (int m = 0; m < 16; ++m) { sr[m] = 0.f; si[m] = 0.f; }
        sr[j] = 1.f;

        for (int l = 0; l < 2; ++l) {
            for (int i = 0; i < 4; ++i) {
                const int st = 8 >> i;
                float th, cc, ss;
                // RX(theta)
                th = qw[(l * 4 + i) * 3 + 0];
                sincosf(0.5f * th, &ss, &cc);
                for (int m = 0; m < 16; ++m) if (!(m & st)) {
                    const int m2 = m | st;
                    float ar = sr[m],  ai = si[m];
                    float br_ = sr[m2], bi = si[m2];
                    sr[m]  = cc * ar + ss * bi;  si[m]  = cc * ai - ss * br_;
                    sr[m2] = cc * br_ + ss * ai; si[m2] = cc * bi - ss * ar;
                }
                // RY(theta)
                th = qw[(l * 4 + i) * 3 + 1];
                sincosf(0.5f * th, &ss, &cc);
                for (int m = 0; m < 16; ++m) if (!(m & st)) {
                    const int m2 = m | st;
                    float ar = sr[m],  ai = si[m];
                    float br_ = sr[m2], bi = si[m2];
                    sr[m]  = cc * ar - ss * br_; si[m]  = cc * ai - ss * bi;
                    sr[m2] = ss * ar + cc * br_; si[m2] = ss * ai + cc * bi;
                }
                // RZ(theta)
                th = qw[(l * 4 + i) * 3 + 2];
                sincosf(0.5f * th, &ss, &cc);
                for (int m = 0; m < 16; ++m) if (!(m & st)) {
                    const int m2 = m | st;
                    float ar = sr[m],  ai = si[m];
                    float br_ = sr[m2], bi = si[m2];
                    sr[m]  = cc * ar + ss * ai;  si[m]  = cc * ai - ss * ar;
                    sr[m2] = cc * br_ - ss * bi; si[m2] = cc * bi + ss * br_;
                }
            }
            // CNOT chain (0,1),(1,2),(2,3) then (3,0)
            for (int e = 0; e < 4; ++e) {
                const int cq = e, tq = (e + 1) & 3;
                const int sc = 8 >> cq, stt = 8 >> tq;
                for (int m = 0; m < 16; ++m) if ((m & sc) && !(m & stt)) {
                    const int m2 = m | stt;
                    float tr = sr[m], ti = si[m];
                    sr[m] = sr[m2];  si[m] = si[m2];
                    sr[m2] = tr;     si[m2] = ti;
                }
            }
        }
        #pragma unroll
        for (int k = 0; k < 16; ++k) { Ur[k][j] = sr[k]; Ui[k][j] = si[k]; }
    }
    __syncthreads();
    if (j < 16) {
        for (int i = 0; i < 16; ++i) {
            float acc = 0.f;
            #pragma unroll
            for (int k = 0; k < 16; ++k) {
                const float d = (k < 8) ? 1.f : -1.f;
                acc += d * (Ur[k][i] * Ur[k][j] + Ui[k][i] * Ui[k][j]);
            }
            d_M[br][i * 16 + j] = acc;
        }
    }
}

// ---------------------------------------------------------------------------
// Fully fused critic kernel. Block = 64 rows; loops over both branches
// (x tiles hit L1/L2 on the second branch). GEMM1 via smem tiles with 8x8
// register blocking; GEMM2 folded into the epilogue with warp reductions;
// quantum expval evaluated as v^T M v with the precomputed M.
// ---------------------------------------------------------------------------
__global__ __launch_bounds__(NTHREADS, 2)
void critic_kernel(const float* __restrict__ state,
                   const float* __restrict__ action,
                   const float* __restrict__ W1a, const float* __restrict__ b1a,
                   const float* __restrict__ W2a, const float* __restrict__ b2a,
                   const float* __restrict__ W1b, const float* __restrict__ b1b,
                   const float* __restrict__ W2b, const float* __restrict__ b2b,
                   const float* __restrict__ pwa, const float* __restrict__ pba,
                   const float* __restrict__ pwb, const float* __restrict__ pbb,
                   float* __restrict__ out) {
    // ws: [BK][HDIM] padded to 257 (conflict-free transposed stores)
    __shared__ float ws[BK * 257];
    // xs: [BK][ROWS] padded to 65; reused as epilogue tables (needs 1792 <= 2080)
    __shared__ float xs[BK * 65];

    const int tid  = threadIdx.x;
    const int ty   = tid >> 5;      // 0..7  (warp id)
    const int tx   = tid & 31;      // lane
    const int row0 = ty * 8;        // this thread's 8 rows
    const int rowbase = blockIdx.x * ROWS;

    for (int br = 0; br < 2; ++br) {
        const float* W1 = br ? W1b : W1a;
        const float* b1 = br ? b1b : b1a;
        const float* W2 = br ? W2b : W2a;
        const float* b2 = br ? b2b : b2a;
        const float  pw = br ? pwb[0] : pwa[0];
        const float  pb = br ? pbb[0] : pba[0];

        float acc[8][8];
        #pragma unroll
        for (int i = 0; i < 8; ++i)
            #pragma unroll
            for (int j = 0; j < 8; ++j) acc[i][j] = 0.f;

        for (int t = 0; t < 5; ++t) {
            const int k0 = t * BK;
            const float* src    = (t < 4) ? state : action;
            const int    stride = (t < 4) ? SD : AD;
            const int    koff   = (t < 4) ? k0 : 0;

            // x tile -> xs[kk][row]   (coalesced global reads, conflict-free stores)
            #pragma unroll
            for (int i = 0; i < 8; ++i) {
                const int e  = tid + i * NTHREADS;
                const int r  = e >> 5;
                const int kk = e & 31;
                xs[kk * 65 + r] = src[(rowbase + r) * stride + koff + kk];
            }
            // W1 tile -> ws[kk][c]
            #pragma unroll
            for (int i = 0; i < 32; ++i) {
                const int e  = tid + i * NTHREADS;
                const int c  = e >> 5;
                const int kk = e & 31;
                ws[kk * 257 + c] = W1[c * XD + k0 + kk];
            }
            __syncthreads();

            #pragma unroll 4
            for (int kk = 0; kk < BK; ++kk) {
                float a[8], bb[8];
                #pragma unroll
                for (int i = 0; i < 8; ++i) a[i] = xs[kk * 65 + row0 + i];
                #pragma unroll
                for (int j = 0; j < 8; ++j) bb[j] = ws[kk * 257 + tx + 32 * j];
                #pragma unroll
                for (int i = 0; i < 8; ++i)
                    #pragma unroll
                    for (int j = 0; j < 8; ++j)
                        acc[i][j] = fmaf(a[i], bb[j], acc[i][j]);
            }
            __syncthreads();
        }

        // Epilogue tables alias xs (GEMM tiles are dead now)
        float* w2s  = xs;          // 1024 floats
        float* b1s  = xs + 1024;   // 256
        float* Ms   = xs + 1280;   // 256
        float* qins = xs + 1536;   // 256
        for (int e = tid; e < 1024; e += NTHREADS) w2s[e] = W2[e];
        {
            b1s[tid & 255] = b1[tid & 255];   // 256 threads, 256 entries
            Ms[tid & 255]  = d_M[br][tid & 255];
        }
        __syncthreads();

        // GEMM2 partials: qp[i][q] = sum over this thread's 8 cols of h*W2[q][c]
        float qp[8][4];
        #pragma unroll
        for (int i = 0; i < 8; ++i)
            #pragma unroll
            for (int q = 0; q < 4; ++q) qp[i][q] = 0.f;

        #pragma unroll
        for (int j = 0; j < 8; ++j) {
            const int c = tx + 32 * j;
            const float bb  = b1s[c];
            const float w0v = w2s[0 * HDIM + c];
            const float w1v = w2s[1 * HDIM + c];
            const float w2v = w2s[2 * HDIM + c];
            const float w3v = w2s[3 * HDIM + c];
            #pragma unroll
            for (int i = 0; i < 8; ++i) {
                const float h = fmaxf(acc[i][j] + bb, 0.f);
                qp[i][0] = fmaf(h, w0v, qp[i][0]);
                qp[i][1] = fmaf(h, w1v, qp[i][1]);
                qp[i][2] = fmaf(h, w2v, qp[i][2]);
                qp[i][3] = fmaf(h, w3v, qp[i][3]);
            }
        }

        // Warp-reduce over the 32 col-threads (warp == fixed ty)
        #pragma unroll
        for (int i = 0; i < 8; ++i)
            #pragma unroll
            for (int q = 0; q < 4; ++q) {
                float v = qp[i][q];
                v += __shfl_xor_sync(0xffffffffu, v, 16);
                v += __shfl_xor_sync(0xffffffffu, v, 8);
                v += __shfl_xor_sync(0xffffffffu, v, 4);
                v += __shfl_xor_sync(0xffffffffu, v, 2);
                v += __shfl_xor_sync(0xffffffffu, v, 1);
                if (tx == 0) qins[(row0 + i) * 4 + q] = v + b2[q];
            }
        __syncthreads();

        // Quantum expval + output affine: one thread per row
        if (tid < ROWS) {
            float cs[4][2];
            #pragma unroll
            for (int i = 0; i < 4; ++i)
                sincosf(0.5f * qins[tid * 4 + i], &cs[i][1], &cs[i][0]);
            float v[16];
            #pragma unroll
            for (int idx = 0; idx < 16; ++idx)
                v[idx] = cs[0][(idx >> 3) & 1] * cs[1][(idx >> 2) & 1]
                       * cs[2][(idx >> 1) & 1] * cs[3][idx & 1];
            float qo = 0.f;
            #pragma unroll
            for (int i = 0; i < 16; ++i) {
                float mv = 0.f;
                #pragma unroll
                for (int j = 0; j < 16; ++j)
                    mv = fmaf(Ms[i * 16 + j], v[j], mv);
                qo = fmaf(v[i], mv, qo);
            }
            out[br * B_TOTAL + rowbase + tid] = fmaf(qo, pw, pb);
        }
        __syncthreads();   // protect smem before next branch
    }
}

extern "C" void kernel_launch(void* const* d_in, const int* in_sizes, int n_in,
                              void* d_out, int out_size) {
    const float* state  = (const float*)d_in[0];
    const float* action = (const float*)d_in[1];
    const float* q1_W1  = (const float*)d_in[2];
    const float* q1_b1  = (const float*)d_in[3];
    const float* q1_W2  = (const float*)d_in[4];
    const float* q1_b2  = (const float*)d_in[5];
    const float* q2_W1  = (const float*)d_in[6];
    const float* q2_b1  = (const float*)d_in[7];
    const float* q2_W2  = (const float*)d_in[8];
    const float* q2_b2  = (const float*)d_in[9];
    const float* q1_qw  = (const float*)d_in[10];
    const float* q2_qw  = (const float*)d_in[11];
    const float* q1_pw  = (const float*)d_in[12];
    const float* q1_pb  = (const float*)d_in[13];
    const float* q2_pw  = (const float*)d_in[14];
    const float* q2_pb  = (const float*)d_in[15];
    float* out = (float*)d_out;

    setup_M_kernel<<<2, 16>>>(q1_qw, q2_qw);
    critic_kernel<<<B_TOTAL / ROWS, NTHREADS>>>(
        state, action,
        q1_W1, q1_b1, q1_W2, q1_b2,
        q2_W1, q2_b1, q2_W2, q2_b2,
        q1_pw, q1_pb, q2_pw, q2_pb,
        out);
}

// round 4
// speedup vs baseline: 5.8288x; 5.8288x over previous
#include <cuda_runtime.h>
#include <math.h>
#include <cstdint>

#define B_TOTAL 131072
#define SD 128
#define AD 32
#define TILE_M 64
#define NTHREADS 256
#define NCHUNK 5

__device__ float d_M[2][256];
// [br][ks(20)][ntile(32)][lane(32)][2] — mma B fragments, tf32-rounded
__device__ float d_Bfrag[2 * 20 * 32 * 32 * 2];

// ---- smem layout (float offsets) ----
#define F_A0    0
#define F_A1    2304          // A buf: [64][36]
#define F_B0    4608          // B buf: 4 ksteps * 32 ntiles * 32 lanes * 2
#define F_B1    12800
#define F_W2S   20992
#define F_B1S   22016
#define F_MS    22272
#define F_QPART 22528         // [8][64][4]
#define F_QIN   24576
#define F_B2S   24832
#define F_PP    24836
#define SMEM_FLOATS 24840
#define SMEM_BYTES (SMEM_FLOATS * 4)

__device__ __forceinline__ uint32_t smem_u32(const void* p) {
    uint32_t a;
    asm("{ .reg .u64 t; cvta.to.shared.u64 t, %1; cvt.u32.u64 %0, t; }" : "=r"(a) : "l"(p));
    return a;
}
__device__ __forceinline__ float tf32r(float x) {
    uint32_t u;
    asm("cvt.rna.tf32.f32 %0, %1;" : "=r"(u) : "f"(x));
    return __uint_as_float(u);
}
#define CP_ASYNC16(dst, src) \
    asm volatile("cp.async.cg.shared.global [%0], [%1], 16;" :: "r"(dst), "l"(src) : "memory")
#define CP_COMMIT() asm volatile("cp.async.commit_group;" ::: "memory")
#define CP_WAIT0()  asm volatile("cp.async.wait_group 0;" ::: "memory")
#define CP_WAIT1()  asm volatile("cp.async.wait_group 1;" ::: "memory")

__device__ __forceinline__ void mma_tf32(float* d, const uint32_t* a,
                                         uint32_t b0, uint32_t b1) {
    asm volatile(
        "mma.sync.aligned.m16n8k8.row.col.f32.tf32.tf32.f32 "
        "{%0,%1,%2,%3}, {%4,%5,%6,%7}, {%8,%9}, {%0,%1,%2,%3};"
        : "+f"(d[0]), "+f"(d[1]), "+f"(d[2]), "+f"(d[3])
        : "r"(a[0]), "r"(a[1]), "r"(a[2]), "r"(a[3]), "r"(b0), "r"(b1));
}

// ---------------------------------------------------------------------------
// Setup: 16x16 Hermitian form M = Re(U^dag Z0 U) per branch.
// ---------------------------------------------------------------------------
__global__ void setup_M_kernel(const float* __restrict__ qw1,
                               const float* __restrict__ qw2) {
    const int br = blockIdx.x;
    const int j  = threadIdx.x;
    const float* qw = br ? qw2 : qw1;
    __shared__ float Ur[16][16];
    __shared__ float Ui[16][16];

    if (j < 16) {
        float sr[16], si[16];
        #pragma unroll
        for (int m = 0; m < 16; ++m) { sr[m] = 0.f; si[m] = 0.f; }
        sr[j] = 1.f;
        for (int l = 0; l < 2; ++l) {
            for (int i = 0; i < 4; ++i) {
                const int st = 8 >> i;
                float th, cc, ss;
                th = qw[(l * 4 + i) * 3 + 0];
                sincosf(0.5f * th, &ss, &cc);
                for (int m = 0; m < 16; ++m) if (!(m & st)) {
                    const int m2 = m | st;
                    float ar = sr[m], ai = si[m], br_ = sr[m2], bi = si[m2];
                    sr[m]  = cc * ar + ss * bi;  si[m]  = cc * ai - ss * br_;
                    sr[m2] = cc * br_ + ss * ai; si[m2] = cc * bi - ss * ar;
                }
                th = qw[(l * 4 + i) * 3 + 1];
                sincosf(0.5f * th, &ss, &cc);
                for (int m = 0; m < 16; ++m) if (!(m & st)) {
                    const int m2 = m | st;
                    float ar = sr[m], ai = si[m], br_ = sr[m2], bi = si[m2];
                    sr[m]  = cc * ar - ss * br_; si[m]  = cc * ai - ss * bi;
                    sr[m2] = ss * ar + cc * br_; si[m2] = ss * ai + cc * bi;
                }
                th = qw[(l * 4 + i) * 3 + 2];
                sincosf(0.5f * th, &ss, &cc);
                for (int m = 0; m < 16; ++m) if (!(m & st)) {
                    const int m2 = m | st;
                    float ar = sr[m], ai = si[m], br_ = sr[m2], bi = si[m2];
                    sr[m]  = cc * ar + ss * ai;  si[m]  = cc * ai - ss * ar;
                    sr[m2] = cc * br_ - ss * bi; si[m2] = cc * bi + ss * br_;
                }
            }
            for (int e = 0; e < 4; ++e) {
                const int cq = e, tq = (e + 1) & 3;
                const int sc = 8 >> cq, stt = 8 >> tq;
                for (int m = 0; m < 16; ++m) if ((m & sc) && !(m & stt)) {
                    const int m2 = m | stt;
                    float tr = sr[m], ti = si[m];
                    sr[m] = sr[m2]; si[m] = si[m2];
                    sr[m2] = tr;    si[m2] = ti;
                }
            }
        }
        #pragma unroll
        for (int k = 0; k < 16; ++k) { Ur[k][j] = sr[k]; Ui[k][j] = si[k]; }
    }
    __syncthreads();
    if (j < 16) {
        for (int i = 0; i < 16; ++i) {
            float acc = 0.f;
            #pragma unroll
            for (int k = 0; k < 16; ++k) {
                const float d = (k < 8) ? 1.f : -1.f;
                acc += d * (Ur[k][i] * Ur[k][j] + Ui[k][i] * Ui[k][j]);
            }
            d_M[br][i * 16 + j] = acc;
        }
    }
}

// ---------------------------------------------------------------------------
// Setup: W1 -> mma B-fragment layout (tf32-rounded).
// b0 = W1[n][ks*8 + lane%4], b1 = W1[n][ks*8 + 4 + lane%4], n = ntile*8 + lane/4
// ---------------------------------------------------------------------------
__global__ void setup_Bfrag_kernel(const float* __restrict__ W1a,
                                   const float* __restrict__ W1b) {
    const int idx = blockIdx.x * 256 + threadIdx.x;
    if (idx >= 2 * 20 * 32 * 32) return;
    const int lane  = idx & 31;
    const int ntile = (idx >> 5) & 31;
    const int t     = idx >> 10;       // br*20 + ks
    const int ks    = t % 20;
    const int br    = t / 20;
    const float* W1 = br ? W1b : W1a;
    const int n = ntile * 8 + (lane >> 2);
    const int k = ks * 8 + (lane & 3);
    d_Bfrag[idx * 2]     = tf32r(W1[n * 160 + k]);
    d_Bfrag[idx * 2 + 1] = tf32r(W1[n * 160 + k + 4]);
}

// ---------------------------------------------------------------------------
// Fused critic via warp-level tf32 mma.sync.
// CTA = 64 rows of one branch; 8 warps each own a 32-col slab.
// ---------------------------------------------------------------------------
__global__ __launch_bounds__(NTHREADS, 2)
void critic_mma(const float* __restrict__ state,
                const float* __restrict__ action,
                const float* __restrict__ b1a, const float* __restrict__ W2a,
                const float* __restrict__ b2a,
                const float* __restrict__ b1b, const float* __restrict__ W2b,
                const float* __restrict__ b2b,
                const float* __restrict__ pwa, const float* __restrict__ pba,
                const float* __restrict__ pwb, const float* __restrict__ pbb,
                float* __restrict__ out) {
    extern __shared__ float sm[];
    const uint32_t sb = smem_u32(sm);
    const int tid  = threadIdx.x;
    const int w    = tid >> 5;
    const int lane = tid & 31;
    const int gid  = lane >> 2;     // group id (row within tile)
    const int tig  = lane & 3;      // thread in group (col pair)
    const int br      = blockIdx.x & 1;
    const int rowbase = (blockIdx.x >> 1) * TILE_M;

    const float* b1 = br ? b1b : b1a;
    const float* W2 = br ? W2b : W2a;
    const float* b2 = br ? b2b : b2a;
    const float* pw = br ? pwb : pwa;
    const float* pb = br ? pbb : pba;

    float* W2s   = sm + F_W2S;
    float* b1s   = sm + F_B1S;
    float* Ms    = sm + F_MS;
    float* qpart = sm + F_QPART;
    float* qin   = sm + F_QIN;
    float* b2s   = sm + F_B2S;
    float* pp    = sm + F_PP;

    // --- staging helpers ---
    // A tile: 64 rows x 32 cols = 512 float4 segs; 8 segs (of 4 floats) per row.
    float4 aregs[2];
    auto ldgA = [&](int c) {
        #pragma unroll
        for (int i = 0; i < 2; ++i) {
            const int e = tid + i * NTHREADS;
            const int r = e >> 3, seg = e & 7;          // FIXED: 8 segs/row
            const float* src = (c < 4)
                ? state  + (size_t)(rowbase + r) * SD + c * 32 + seg * 4
                : action + (size_t)(rowbase + r) * AD + seg * 4;
            aregs[i] = *(const float4*)src;
        }
    };
    auto stsA = [&](float* As) {
        #pragma unroll
        for (int i = 0; i < 2; ++i) {
            const int e = tid + i * NTHREADS;
            const int r = e >> 3, seg = e & 7;          // FIXED: 8 segs/row
            float4 v = aregs[i];
            v.x = tf32r(v.x); v.y = tf32r(v.y); v.z = tf32r(v.z); v.w = tf32r(v.w);
            *(float4*)(As + r * 36 + seg * 4) = v;
        }
    };
    auto loadB = [&](int c, int foff) {
        const float* src = d_Bfrag + ((size_t)br * 5 + c) * 8192;
        const uint32_t dst = sb + foff * 4;
        #pragma unroll
        for (int i = 0; i < 8; ++i) {
            const int e = tid + i * NTHREADS;   // 0..2047 (16B segs)
            CP_ASYNC16(dst + e * 16, src + e * 4);
        }
    };

    // --- prologue ---
    ldgA(0); stsA(sm + F_A0);
    ldgA(1);
    loadB(0, F_B0); CP_COMMIT();
    loadB(1, F_B1); CP_COMMIT();

    #pragma unroll
    for (int i = 0; i < 4; ++i) W2s[tid + i * NTHREADS] = W2[tid + i * NTHREADS];
    b1s[tid & 255] = b1[tid & 255];
    Ms[tid & 255]  = d_M[br][tid & 255];
    if (tid < 4) b2s[tid] = b2[tid];
    if (tid == 0) { pp[0] = pw[0]; pp[1] = pb[0]; }

    float acc[4][4][4];
    #pragma unroll
    for (int mt = 0; mt < 4; ++mt)
        #pragma unroll
        for (int nt = 0; nt < 4; ++nt)
            #pragma unroll
            for (int i = 0; i < 4; ++i) acc[mt][nt][i] = 0.f;

    // --- main K loop: 5 chunks x 4 ksteps of 8 ---
    for (int c = 0; c < NCHUNK; ++c) {
        if (c < NCHUNK - 1) CP_WAIT1(); else CP_WAIT0();
        __syncthreads();

        const float* As = sm + ((c & 1) ? F_A1 : F_A0);
        const float* Bs = sm + ((c & 1) ? F_B1 : F_B0);

        #pragma unroll
        for (int kis = 0; kis < 4; ++kis) {
            uint32_t a[4][4];
            #pragma unroll
            for (int mt = 0; mt < 4; ++mt) {
                const float* ap = As + (mt * 16 + gid) * 36 + kis * 8 + tig;
                a[mt][0] = __float_as_uint(ap[0]);
                a[mt][2] = __float_as_uint(ap[4]);
                a[mt][1] = __float_as_uint(ap[8 * 36]);
                a[mt][3] = __float_as_uint(ap[8 * 36 + 4]);
            }
            #pragma unroll
            for (int nt = 0; nt < 4; ++nt) {
                const float2 bv = *(const float2*)(Bs + ((kis * 32 + w * 4 + nt) * 32 + lane) * 2);
                const uint32_t b0 = __float_as_uint(bv.x);
                const uint32_t b1f = __float_as_uint(bv.y);
                #pragma unroll
                for (int mt = 0; mt < 4; ++mt)
                    mma_tf32(acc[mt][nt], a[mt], b0, b1f);
            }
        }
        __syncthreads();
        if (c + 1 < NCHUNK) {
            stsA(sm + (((c + 1) & 1) ? F_A1 : F_A0));
            if (c + 2 < NCHUNK) {
                ldgA(c + 2);
                loadB(c + 2, (c & 1) ? F_B1 : F_B0);
                CP_COMMIT();
            }
        }
    }

    // --- epilogue: relu + b1, fold W2 (qin partials per thread) ---
    float qpa[4][4], qpb[4][4];   // [mt][q] for rows gid and gid+8
    #pragma unroll
    for (int mt = 0; mt < 4; ++mt)
        #pragma unroll
        for (int q = 0; q < 4; ++q) { qpa[mt][q] = 0.f; qpb[mt][q] = 0.f; }

    #pragma unroll
    for (int nt = 0; nt < 4; ++nt) {
        const int c0 = w * 32 + nt * 8 + tig * 2;
        const float bb0 = b1s[c0], bb1 = b1s[c0 + 1];
        #pragma unroll
        for (int q = 0; q < 4; ++q) {
            const float w20 = W2s[q * 256 + c0];
            const float w21 = W2s[q * 256 + c0 + 1];
            #pragma unroll
            for (int mt = 0; mt < 4; ++mt) {
                const float ha0 = fmaxf(acc[mt][nt][0] + bb0, 0.f);
                const float ha1 = fmaxf(acc[mt][nt][1] + bb1, 0.f);
                const float hb0 = fmaxf(acc[mt][nt][2] + bb0, 0.f);
                const float hb1 = fmaxf(acc[mt][nt][3] + bb1, 0.f);
                qpa[mt][q] = fmaf(ha0, w20, fmaf(ha1, w21, qpa[mt][q]));
                qpb[mt][q] = fmaf(hb0, w20, fmaf(hb1, w21, qpb[mt][q]));
            }
        }
    }

    // quad reduce (over tig) then per-warp store
    #pragma unroll
    for (int mt = 0; mt < 4; ++mt)
        #pragma unroll
        for (int q = 0; q < 4; ++q) {
            float va = qpa[mt][q];
            va += __shfl_xor_sync(0xffffffffu, va, 1);
            va += __shfl_xor_sync(0xffffffffu, va, 2);
            float vb = qpb[mt][q];
            vb += __shfl_xor_sync(0xffffffffu, vb, 1);
            vb += __shfl_xor_sync(0xffffffffu, vb, 2);
            if (tig == 0) {
                qpart[(w * 64 + mt * 16 + gid) * 4 + q]     = va;
                qpart[(w * 64 + mt * 16 + gid + 8) * 4 + q] = vb;
            }
        }
    __syncthreads();

    // cross-warp reduce: 256 threads cover 64 rows x 4 q
    {
        float s = 0.f;
        #pragma unroll
        for (int ww = 0; ww < 8; ++ww) s += qpart[ww * 256 + tid];
        qin[tid] = s + b2s[tid & 3];
    }
    __syncthreads();

    // quantum expval v^T M v + output affine (64 threads)
    if (tid < TILE_M) {
        float cs[4][2];
        #pragma unroll
        for (int i = 0; i < 4; ++i)
            sincosf(0.5f * qin[tid * 4 + i], &cs[i][1], &cs[i][0]);
        float v[16];
        #pragma unroll
        for (int idx = 0; idx < 16; ++idx)
            v[idx] = cs[0][(idx >> 3) & 1] * cs[1][(idx >> 2) & 1]
                   * cs[2][(idx >> 1) & 1] * cs[3][idx & 1];
        float qo = 0.f;
        #pragma unroll
        for (int i = 0; i < 16; ++i) {
            float mv = 0.f;
            #pragma unroll
            for (int j = 0; j < 16; ++j)
                mv = fmaf(Ms[i * 16 + j], v[j], mv);
            qo = fmaf(v[i], mv, qo);
        }
        out[br * B_TOTAL + rowbase + tid] = fmaf(qo, pp[0], pp[1]);
    }
}

extern "C" void kernel_launch(void* const* d_in, const int* in_sizes, int n_in,
                              void* d_out, int out_size) {
    const float* state  = (const float*)d_in[0];
    const float* action = (const float*)d_in[1];
    const float* q1_W1  = (const float*)d_in[2];
    const float* q1_b1  = (const float*)d_in[3];
    const float* q1_W2  = (const float*)d_in[4];
    const float* q1_b2  = (const float*)d_in[5];
    const float* q2_W1  = (const float*)d_in[6];
    const float* q2_b1  = (const float*)d_in[7];
    const float* q2_W2  = (const float*)d_in[8];
    const float* q2_b2  = (const float*)d_in[9];
    const float* q1_qw  = (const float*)d_in[10];
    const float* q2_qw  = (const float*)d_in[11];
    const float* q1_pw  = (const float*)d_in[12];
    const float* q1_pb  = (const float*)d_in[13];
    const float* q2_pw  = (const float*)d_in[14];
    const float* q2_pb  = (const float*)d_in[15];
    float* out = (float*)d_out;

    cudaFuncSetAttribute(critic_mma, cudaFuncAttributeMaxDynamicSharedMemorySize,
                         SMEM_BYTES);

    setup_M_kernel<<<2, 16>>>(q1_qw, q2_qw);
    setup_Bfrag_kernel<<<160, 256>>>(q1_W1, q2_W1);
    critic_mma<<<(B_TOTAL / TILE_M) * 2, NTHREADS, SMEM_BYTES>>>(
        state, action,
        q1_b1, q1_W2, q1_b2,
        q2_b1, q2_W2, q2_b2,
        q1_pw, q1_pb, q2_pw, q2_pb,
        out);
}

// round 5
// speedup vs baseline: 8.0228x; 1.3764x over previous
#include <cuda_runtime.h>
#include <cuda_fp16.h>
#include <math.h>
#include <cstdint>

#define B_TOTAL 131072
#define SD 128
#define AD 32
#define TILE_M 128
#define NTHREADS 512
#define NCHUNK 5

__device__ float d_M[2][256];
// fp16 B fragments: [br][ks(10)][ntile(32)][lane(32)][2 regs] as half2
__device__ __half2 d_Bfrag[2 * 10 * 32 * 32 * 2];

// ---- smem layout (byte offsets) ----
#define OFF_A0    0          // [128][40] halfs = 10240B
#define OFF_A1    10240
#define OFF_B0    20480      // 16KB per chunk
#define OFF_B1    36864
#define OFF_W2S   53248      // 1024 floats
#define OFF_B1S   57344      // 256 floats
#define OFF_MS    58368      // 256 floats
#define OFF_QPART 59392      // [4][128][4] floats = 8KB
#define OFF_QIN   67584      // 512 floats
#define OFF_B2S   69632      // 4 floats
#define OFF_PP    69648      // 2 floats
#define SMEM_BYTES 69664

#define A_PITCH 40           // halfs per row (32 data + 8 pad)

__device__ __forceinline__ uint32_t smem_u32(const void* p) {
    uint32_t a;
    asm("{ .reg .u64 t; cvta.to.shared.u64 t, %1; cvt.u32.u64 %0, t; }" : "=r"(a) : "l"(p));
    return a;
}
#define CP_ASYNC16(dst, src) \
    asm volatile("cp.async.cg.shared.global [%0], [%1], 16;" :: "r"(dst), "l"(src) : "memory")
#define CP_COMMIT() asm volatile("cp.async.commit_group;" ::: "memory")
#define CP_WAIT0()  asm volatile("cp.async.wait_group 0;" ::: "memory")
#define CP_WAIT1()  asm volatile("cp.async.wait_group 1;" ::: "memory")

__device__ __forceinline__ void mma_f16(float* d, const uint32_t* a,
                                        uint32_t b0, uint32_t b1) {
    asm volatile(
        "mma.sync.aligned.m16n8k16.row.col.f32.f16.f16.f32 "
        "{%0,%1,%2,%3}, {%4,%5,%6,%7}, {%8,%9}, {%0,%1,%2,%3};"
        : "+f"(d[0]), "+f"(d[1]), "+f"(d[2]), "+f"(d[3])
        : "r"(a[0]), "r"(a[1]), "r"(a[2]), "r"(a[3]), "r"(b0), "r"(b1));
}

// ---------------------------------------------------------------------------
// Merged setup: blocks 0,1 -> 16x16 Hermitian form M; blocks 2+ -> B frags.
// ---------------------------------------------------------------------------
__global__ void setup_kernel(const float* __restrict__ qw1,
                             const float* __restrict__ qw2,
                             const float* __restrict__ W1a,
                             const float* __restrict__ W1b) {
    if (blockIdx.x < 2) {
        const int br = blockIdx.x;
        const int j  = threadIdx.x;
        const float* qw = br ? qw2 : qw1;
        __shared__ float Ur[16][16];
        __shared__ float Ui[16][16];

        if (j < 16) {
            float sr[16], si[16];
            #pragma unroll
            for (int m = 0; m < 16; ++m) { sr[m] = 0.f; si[m] = 0.f; }
            sr[j] = 1.f;
            for (int l = 0; l < 2; ++l) {
                for (int i = 0; i < 4; ++i) {
                    const int st = 8 >> i;
                    float th, cc, ss;
                    th = qw[(l * 4 + i) * 3 + 0];
                    sincosf(0.5f * th, &ss, &cc);
                    for (int m = 0; m < 16; ++m) if (!(m & st)) {
                        const int m2 = m | st;
                        float ar = sr[m], ai = si[m], br_ = sr[m2], bi = si[m2];
                        sr[m]  = cc * ar + ss * bi;  si[m]  = cc * ai - ss * br_;
                        sr[m2] = cc * br_ + ss * ai; si[m2] = cc * bi - ss * ar;
                    }
                    th = qw[(l * 4 + i) * 3 + 1];
                    sincosf(0.5f * th, &ss, &cc);
                    for (int m = 0; m < 16; ++m) if (!(m & st)) {
                        const int m2 = m | st;
                        float ar = sr[m], ai = si[m], br_ = sr[m2], bi = si[m2];
                        sr[m]  = cc * ar - ss * br_; si[m]  = cc * ai - ss * bi;
                        sr[m2] = ss * ar + cc * br_; si[m2] = ss * ai + cc * bi;
                    }
                    th = qw[(l * 4 + i) * 3 + 2];
                    sincosf(0.5f * th, &ss, &cc);
                    for (int m = 0; m < 16; ++m) if (!(m & st)) {
                        const int m2 = m | st;
                        float ar = sr[m], ai = si[m], br_ = sr[m2], bi = si[m2];
                        sr[m]  = cc * ar + ss * ai;  si[m]  = cc * ai - ss * ar;
                        sr[m2] = cc * br_ - ss * bi; si[m2] = cc * bi + ss * br_;
                    }
                }
                for (int e = 0; e < 4; ++e) {
                    const int cq = e, tq = (e + 1) & 3;
                    const int sc = 8 >> cq, stt = 8 >> tq;
                    for (int m = 0; m < 16; ++m) if ((m & sc) && !(m & stt)) {
                        const int m2 = m | stt;
                        float tr = sr[m], ti = si[m];
                        sr[m] = sr[m2]; si[m] = si[m2];
                        sr[m2] = tr;    si[m2] = ti;
                    }
                }
            }
            #pragma unroll
            for (int k = 0; k < 16; ++k) { Ur[k][j] = sr[k]; Ui[k][j] = si[k]; }
        }
        __syncthreads();
        if (j < 16) {
            for (int i = 0; i < 16; ++i) {
                float acc = 0.f;
                #pragma unroll
                for (int k = 0; k < 16; ++k) {
                    const float d = (k < 8) ? 1.f : -1.f;
                    acc += d * (Ur[k][i] * Ur[k][j] + Ui[k][i] * Ui[k][j]);
                }
                d_M[br][i * 16 + j] = acc;
            }
        }
    } else {
        // B fragments for m16n8k16: b0 = {W1[n][16ks+2tig], +1}, b1 = same +8
        const int idx = (blockIdx.x - 2) * 256 + threadIdx.x;
        if (idx >= 2 * 10 * 32 * 32) return;
        const int lane  = idx & 31;
        const int ntile = (idx >> 5) & 31;
        const int t     = idx >> 10;       // br*10 + ks
        const int ks    = t % 10;
        const int br    = t / 10;
        const float* W1 = br ? W1b : W1a;
        const int n  = ntile * 8 + (lane >> 2);
        const int k0 = ks * 16 + (lane & 3) * 2;
        d_Bfrag[idx * 2]     = __floats2half2_rn(W1[n * 160 + k0],     W1[n * 160 + k0 + 1]);
        d_Bfrag[idx * 2 + 1] = __floats2half2_rn(W1[n * 160 + k0 + 8], W1[n * 160 + k0 + 9]);
    }
}

// ---------------------------------------------------------------------------
// Fused critic via warp-level fp16 mma.sync (fp32 accumulate).
// CTA = 128 rows of one branch; 16 warps in 4x4 grid, each 32 rows x 64 cols.
// ---------------------------------------------------------------------------
__global__ __launch_bounds__(NTHREADS, 1)
void critic_mma(const float* __restrict__ state,
                const float* __restrict__ action,
                const float* __restrict__ b1a, const float* __restrict__ W2a,
                const float* __restrict__ b2a,
                const float* __restrict__ b1b, const float* __restrict__ W2b,
                const float* __restrict__ b2b,
                const float* __restrict__ pwa, const float* __restrict__ pba,
                const float* __restrict__ pwb, const float* __restrict__ pbb,
                float* __restrict__ out) {
    extern __shared__ char smem[];
    const uint32_t sb = smem_u32(smem);
    const int tid  = threadIdx.x;
    const int w    = tid >> 5;
    const int lane = tid & 31;
    const int mw   = w >> 2;        // 0..3 row-warp
    const int nw   = w & 3;         // 0..3 col-warp
    const int gid  = lane >> 2;
    const int tig  = lane & 3;
    const int br      = blockIdx.x & 1;
    const int rowbase = (blockIdx.x >> 1) * TILE_M;

    const float* b1 = br ? b1b : b1a;
    const float* W2 = br ? W2b : W2a;
    const float* b2 = br ? b2b : b2a;
    const float* pw = br ? pwb : pwa;
    const float* pb = br ? pbb : pba;

    float* W2s   = (float*)(smem + OFF_W2S);
    float* b1s   = (float*)(smem + OFF_B1S);
    float* Ms    = (float*)(smem + OFF_MS);
    float* qpart = (float*)(smem + OFF_QPART);
    float* qin   = (float*)(smem + OFF_QIN);
    float* b2s   = (float*)(smem + OFF_B2S);
    float* pp    = (float*)(smem + OFF_PP);

    // --- staging helpers ---
    // A chunk: 128 rows x 32 cols fp32 -> fp16 smem [128][A_PITCH]
    float4 aregs[2];
    auto ldgA = [&](int c) {
        #pragma unroll
        for (int i = 0; i < 2; ++i) {
            const int e = tid + i * NTHREADS;       // 0..1023
            const int r = e >> 3, seg = e & 7;
            const float* src = (c < 4)
                ? state  + (size_t)(rowbase + r) * SD + c * 32 + seg * 4
                : action + (size_t)(rowbase + r) * AD + seg * 4;
            aregs[i] = *(const float4*)src;
        }
    };
    auto stsA = [&](__half* As) {
        #pragma unroll
        for (int i = 0; i < 2; ++i) {
            const int e = tid + i * NTHREADS;
            const int r = e >> 3, seg = e & 7;
            const float4 v = aregs[i];
            __half2 h0 = __floats2half2_rn(v.x, v.y);
            __half2 h1 = __floats2half2_rn(v.z, v.w);
            *(uint2*)(As + r * A_PITCH + seg * 4) =
                make_uint2(*(uint32_t*)&h0, *(uint32_t*)&h1);
        }
    };
    auto loadB = [&](int c, uint32_t dst) {
        const __half2* src = d_Bfrag + ((size_t)br * 10 + 2 * c) * 2048;
        #pragma unroll
        for (int i = 0; i < 2; ++i) {
            const int e = tid + i * NTHREADS;   // 0..1023 (16B segs)
            CP_ASYNC16(dst + e * 16, src + e * 4);
        }
    };

    __half* A0 = (__half*)(smem + OFF_A0);
    __half* A1 = (__half*)(smem + OFF_A1);

    // --- prologue ---
    ldgA(0); stsA(A0);
    ldgA(1);
    loadB(0, sb + OFF_B0); CP_COMMIT();
    loadB(1, sb + OFF_B1); CP_COMMIT();

    #pragma unroll
    for (int i = 0; i < 2; ++i) W2s[tid + i * NTHREADS] = W2[tid + i * NTHREADS];
    b1s[tid & 255] = b1[tid & 255];
    Ms[tid & 255]  = d_M[br][tid & 255];
    if (tid < 4) b2s[tid] = b2[tid];
    if (tid == 0) { pp[0] = pw[0]; pp[1] = pb[0]; }

    float acc[2][8][4];
    #pragma unroll
    for (int mt = 0; mt < 2; ++mt)
        #pragma unroll
        for (int nt = 0; nt < 8; ++nt)
            #pragma unroll
            for (int i = 0; i < 4; ++i) acc[mt][nt][i] = 0.f;

    // --- main K loop: 5 chunks x 2 ksteps of 16 ---
    for (int c = 0; c < NCHUNK; ++c) {
        if (c < NCHUNK - 1) CP_WAIT1(); else CP_WAIT0();
        __syncthreads();

        const __half* As = (c & 1) ? A1 : A0;
        const char*   Bs = smem + ((c & 1) ? OFF_B1 : OFF_B0);

        #pragma unroll
        for (int ks = 0; ks < 2; ++ks) {
            uint32_t a[2][4];
            #pragma unroll
            for (int mt = 0; mt < 2; ++mt) {
                const __half* ap = As + (mw * 32 + mt * 16 + gid) * A_PITCH
                                 + ks * 16 + tig * 2;
                a[mt][0] = *(const uint32_t*)(ap);
                a[mt][2] = *(const uint32_t*)(ap + 8);
                a[mt][1] = *(const uint32_t*)(ap + 8 * A_PITCH);
                a[mt][3] = *(const uint32_t*)(ap + 8 * A_PITCH + 8);
            }
            #pragma unroll
            for (int nt = 0; nt < 8; ++nt) {
                const uint2 bv = *(const uint2*)(Bs
                    + (((ks * 32 + nw * 8 + nt) * 32 + lane) * 8));
                #pragma unroll
                for (int mt = 0; mt < 2; ++mt)
                    mma_f16(acc[mt][nt], a[mt], bv.x, bv.y);
            }
        }
        __syncthreads();
        if (c + 1 < NCHUNK) {
            stsA((c + 1) & 1 ? A1 : A0);
            if (c + 2 < NCHUNK) {
                ldgA(c + 2);
                loadB(c + 2, sb + ((c & 1) ? OFF_B1 : OFF_B0));
                CP_COMMIT();
            }
        }
    }

    // --- epilogue: relu + b1, fold W2 ---
    float qp[4][4];   // [mt*2 + half][q]
    #pragma unroll
    for (int r = 0; r < 4; ++r)
        #pragma unroll
        for (int q = 0; q < 4; ++q) qp[r][q] = 0.f;

    #pragma unroll
    for (int nt = 0; nt < 8; ++nt) {
        const int c0 = nw * 64 + nt * 8 + tig * 2;
        const float bb0 = b1s[c0], bb1 = b1s[c0 + 1];
        #pragma unroll
        for (int q = 0; q < 4; ++q) {
            const float w20 = W2s[q * 256 + c0];
            const float w21 = W2s[q * 256 + c0 + 1];
            #pragma unroll
            for (int mt = 0; mt < 2; ++mt) {
                const float h00 = fmaxf(acc[mt][nt][0] + bb0, 0.f);
                const float h01 = fmaxf(acc[mt][nt][1] + bb1, 0.f);
                const float h10 = fmaxf(acc[mt][nt][2] + bb0, 0.f);
                const float h11 = fmaxf(acc[mt][nt][3] + bb1, 0.f);
                qp[mt * 2][q]     = fmaf(h00, w20, fmaf(h01, w21, qp[mt * 2][q]));
                qp[mt * 2 + 1][q] = fmaf(h10, w20, fmaf(h11, w21, qp[mt * 2 + 1][q]));
            }
        }
    }

    // quad reduce over tig, then per (nw) partial store
    #pragma unroll
    for (int r = 0; r < 4; ++r)
        #pragma unroll
        for (int q = 0; q < 4; ++q) {
            float v = qp[r][q];
            v += __shfl_xor_sync(0xffffffffu, v, 1);
            v += __shfl_xor_sync(0xffffffffu, v, 2);
            if (tig == 0) {
                const int mt = r >> 1, half = r & 1;
                const int row = mw * 32 + mt * 16 + half * 8 + gid;
                qpart[(nw * 128 + row) * 4 + q] = v;
            }
        }
    __syncthreads();

    // cross-warp reduce: 512 threads cover 128 rows x 4 q
    {
        const int row = tid >> 2, q = tid & 3;
        float s = 0.f;
        #pragma unroll
        for (int ww = 0; ww < 4; ++ww) s += qpart[(ww * 128 + row) * 4 + q];
        qin[tid] = s + b2s[q];
    }
    __syncthreads();

    // quantum expval v^T M v + output affine (128 threads)
    if (tid < TILE_M) {
        float cs[4][2];
        #pragma unroll
        for (int i = 0; i < 4; ++i)
            sincosf(0.5f * qin[tid * 4 + i], &cs[i][1], &cs[i][0]);
        float v[16];
        #pragma unroll
        for (int idx = 0; idx < 16; ++idx)
            v[idx] = cs[0][(idx >> 3) & 1] * cs[1][(idx >> 2) & 1]
                   * cs[2][(idx >> 1) & 1] * cs[3][idx & 1];
        float qo = 0.f;
        #pragma unroll
        for (int i = 0; i < 16; ++i) {
            float mv = 0.f;
            #pragma unroll
            for (int j = 0; j < 16; ++j)
                mv = fmaf(Ms[i * 16 + j], v[j], mv);
            qo = fmaf(v[i], mv, qo);
        }
        out[br * B_TOTAL + rowbase + tid] = fmaf(qo, pp[0], pp[1]);
    }
}

extern "C" void kernel_launch(void* const* d_in, const int* in_sizes, int n_in,
                              void* d_out, int out_size) {
    const float* state  = (const float*)d_in[0];
    const float* action = (const float*)d_in[1];
    const float* q1_W1  = (const float*)d_in[2];
    const float* q1_b1  = (const float*)d_in[3];
    const float* q1_W2  = (const float*)d_in[4];
    const float* q1_b2  = (const float*)d_in[5];
    const float* q2_W1  = (const float*)d_in[6];
    const float* q2_b1  = (const float*)d_in[7];
    const float* q2_W2  = (const float*)d_in[8];
    const float* q2_b2  = (const float*)d_in[9];
    const float* q1_qw  = (const float*)d_in[10];
    const float* q2_qw  = (const float*)d_in[11];
    const float* q1_pw  = (const float*)d_in[12];
    const float* q1_pb  = (const float*)d_in[13];
    const float* q2_pw  = (const float*)d_in[14];
    const float* q2_pb  = (const float*)d_in[15];
    float* out = (float*)d_out;

    cudaFuncSetAttribute(critic_mma, cudaFuncAttributeMaxDynamicSharedMemorySize,
                         SMEM_BYTES);

    setup_kernel<<<82, 256>>>(q1_qw, q2_qw, q1_W1, q2_W1);
    critic_mma<<<(B_TOTAL / TILE_M) * 2, NTHREADS, SMEM_BYTES>>>(
        state, action,
        q1_b1, q1_W2, q1_b2,
        q2_b1, q2_W2, q2_b2,
        q1_pw, q1_pb, q2_pw, q2_pb,
        out);
}

// round 6
// speedup vs baseline: 10.9819x; 1.3688x over previous
#include <cuda_runtime.h>
#include <cuda_fp16.h>
#include <math.h>
#include <cstdint>

#define B_TOTAL 131072
#define SD 128
#define AD 32
#define TILE_M 128
#define NTILES 1024            // per branch
#define NTHREADS 512

__device__ float d_M[2][256];
// fp16 B fragments: [br][ks(10)][ntile(32)][lane(32)][2 regs] as half2
__device__ __half2 d_Bfrag[2 * 10 * 32 * 32 * 2];

// ---- smem layout (byte offsets) ----
#define OFF_B     0            // 81920B: full B frags
#define OFF_A0    81920        // [128][168] halfs = 43008B
#define OFF_A1    124928
#define OFF_W2S   167936       // 1024 floats
#define OFF_B1S   172032       // 256 floats
#define OFF_MS    173056       // 256 floats
#define OFF_QPART 174080       // [4][128][4] floats
#define OFF_QIN   182272       // 512 floats
#define OFF_B2S   184320
#define OFF_PP    184336
#define SMEM_BYTES 184352

#define A_PITCH 168            // halfs per row (160 data + 8 pad)

__device__ __forceinline__ uint32_t smem_u32(const void* p) {
    uint32_t a;
    asm("{ .reg .u64 t; cvta.to.shared.u64 t, %1; cvt.u32.u64 %0, t; }" : "=r"(a) : "l"(p));
    return a;
}
#define CP_ASYNC16(dst, src) \
    asm volatile("cp.async.cg.shared.global [%0], [%1], 16;" :: "r"(dst), "l"(src) : "memory")
#define CP_COMMIT() asm volatile("cp.async.commit_group;" ::: "memory")
#define CP_WAIT0()  asm volatile("cp.async.wait_group 0;" ::: "memory")

__device__ __forceinline__ void mma_f16(float* d, const uint32_t* a,
                                        uint32_t b0, uint32_t b1) {
    asm volatile(
        "mma.sync.aligned.m16n8k16.row.col.f32.f16.f16.f32 "
        "{%0,%1,%2,%3}, {%4,%5,%6,%7}, {%8,%9}, {%0,%1,%2,%3};"
        : "+f"(d[0]), "+f"(d[1]), "+f"(d[2]), "+f"(d[3])
        : "r"(a[0]), "r"(a[1]), "r"(a[2]), "r"(a[3]), "r"(b0), "r"(b1));
}

// ---------------------------------------------------------------------------
// Merged setup: blocks 0,1 -> M (parallel over 256 threads); blocks 2+ -> Bfrag.
// Thread t of an M block: column j = t>>4, amplitude m = t&15; gate pairs
// exchanged via shfl.xor (partner lane differs only in bits <16).
// ---------------------------------------------------------------------------
__global__ void setup_kernel(const float* __restrict__ qw1,
                             const float* __restrict__ qw2,
                             const float* __restrict__ W1a,
                             const float* __restrict__ W1b) {
    if (blockIdx.x < 2) {
        const int br = blockIdx.x;
        const int t  = threadIdx.x;
        const int j  = t >> 4;
        const int m  = t & 15;
        const float* qw = br ? qw2 : qw1;
        __shared__ float Ur[16][17];
        __shared__ float Ui[16][17];

        float sr = (m == j) ? 1.f : 0.f;
        float si = 0.f;

        for (int l = 0; l < 2; ++l) {
            #pragma unroll
            for (int i = 0; i < 4; ++i) {
                const int st = 8 >> i;
                float cc, ss, pr, pi;
                // RX
                sincosf(0.5f * qw[(l * 4 + i) * 3 + 0], &ss, &cc);
                pr = __shfl_xor_sync(0xffffffffu, sr, st);
                pi = __shfl_xor_sync(0xffffffffu, si, st);
                { float nr = cc * sr + ss * pi, ni = cc * si - ss * pr;
                  sr = nr; si = ni; }
                // RY
                sincosf(0.5f * qw[(l * 4 + i) * 3 + 1], &ss, &cc);
                pr = __shfl_xor_sync(0xffffffffu, sr, st);
                pi = __shfl_xor_sync(0xffffffffu, si, st);
                { const float e = (m & st) ? ss : -ss;
                  float nr = cc * sr + e * pr, ni = cc * si + e * pi;
                  sr = nr; si = ni; }
                // RZ (diagonal)
                sincosf(0.5f * qw[(l * 4 + i) * 3 + 2], &ss, &cc);
                { const float e = (m & st) ? -ss : ss;
                  float nr = cc * sr + e * si, ni = cc * si - e * sr;
                  sr = nr; si = ni; }
            }
            #pragma unroll
            for (int e = 0; e < 4; ++e) {
                const int sc  = 8 >> e;
                const int stt = 8 >> ((e + 1) & 3);
                const float pr = __shfl_xor_sync(0xffffffffu, sr, stt);
                const float pi = __shfl_xor_sync(0xffffffffu, si, stt);
                if (m & sc) { sr = pr; si = pi; }
            }
        }
        Ur[m][j] = sr;
        Ui[m][j] = si;
        __syncthreads();
        {
            const int i = t >> 4, jj = t & 15;
            float acc = 0.f;
            #pragma unroll
            for (int k = 0; k < 16; ++k) {
                const float d = (k < 8) ? 1.f : -1.f;
                acc += d * (Ur[k][i] * Ur[k][jj] + Ui[k][i] * Ui[k][jj]);
            }
            d_M[br][i * 16 + jj] = acc;
        }
    } else {
        const int idx = (blockIdx.x - 2) * 256 + threadIdx.x;
        if (idx >= 2 * 10 * 32 * 32) return;
        const int lane  = idx & 31;
        const int ntile = (idx >> 5) & 31;
        const int t     = idx >> 10;       // br*10 + ks
        const int ks    = t % 10;
        const int br    = t / 10;
        const float* W1 = br ? W1b : W1a;
        const int n  = ntile * 8 + (lane >> 2);
        const int k0 = ks * 16 + (lane & 3) * 2;
        d_Bfrag[idx * 2]     = __floats2half2_rn(W1[n * 160 + k0],     W1[n * 160 + k0 + 1]);
        d_Bfrag[idx * 2 + 1] = __floats2half2_rn(W1[n * 160 + k0 + 8], W1[n * 160 + k0 + 9]);
    }
}

// ---------------------------------------------------------------------------
// Persistent fused critic. One CTA per SM; CTA owns one branch and loops over
// its tile range. B (full W1 frags) loaded to smem once; A double-buffered
// per tile; 10-kstep MMA loop with no barriers.
// ---------------------------------------------------------------------------
__global__ __launch_bounds__(NTHREADS, 1)
void critic_mma(const float* __restrict__ state,
                const float* __restrict__ action,
                const float* __restrict__ b1a, const float* __restrict__ W2a,
                const float* __restrict__ b2a,
                const float* __restrict__ b1b, const float* __restrict__ W2b,
                const float* __restrict__ b2b,
                const float* __restrict__ pwa, const float* __restrict__ pba,
                const float* __restrict__ pwb, const float* __restrict__ pbb,
                float* __restrict__ out) {
    extern __shared__ char smem[];
    const uint32_t sb = smem_u32(smem);
    const int tid  = threadIdx.x;
    const int w    = tid >> 5;
    const int lane = tid & 31;
    const int mw   = w >> 2;
    const int nw   = w & 3;
    const int gid  = lane >> 2;
    const int tig  = lane & 3;

    const int br   = blockIdx.x & 1;
    const int cid  = blockIdx.x >> 1;
    const int ncta = gridDim.x >> 1;
    const int per  = NTILES / ncta;
    const int rem  = NTILES % ncta;
    const int t0   = cid * per + (cid < rem ? cid : rem);
    const int cnt  = per + (cid < rem ? 1 : 0);

    const float* b1 = br ? b1b : b1a;
    const float* W2 = br ? W2b : W2a;
    const float* b2 = br ? b2b : b2a;
    const float* pw = br ? pwb : pwa;
    const float* pb = br ? pbb : pba;

    float* W2s   = (float*)(smem + OFF_W2S);
    float* b1s   = (float*)(smem + OFF_B1S);
    float* Ms    = (float*)(smem + OFF_MS);
    float* qpart = (float*)(smem + OFF_QPART);
    float* qin   = (float*)(smem + OFF_QIN);
    float* b2s   = (float*)(smem + OFF_B2S);
    float* pp    = (float*)(smem + OFF_PP);
    __half* A0   = (__half*)(smem + OFF_A0);
    __half* A1   = (__half*)(smem + OFF_A1);

    // --- A staging: full tile (128 x 160 fp32) -> regs -> fp16 smem ---
    float4 aregs[10];
    auto ldgA = [&](int rowbase) {
        #pragma unroll
        for (int ch = 0; ch < 5; ++ch)
            #pragma unroll
            for (int i = 0; i < 2; ++i) {
                const int e = tid + i * NTHREADS;     // 0..1023
                const int r = e >> 3, seg = e & 7;
                const float* src = (ch < 4)
                    ? state  + (size_t)(rowbase + r) * SD + ch * 32 + seg * 4
                    : action + (size_t)(rowbase + r) * AD + seg * 4;
                aregs[ch * 2 + i] = *(const float4*)src;
            }
    };
    auto stsA = [&](__half* As) {
        #pragma unroll
        for (int ch = 0; ch < 5; ++ch)
            #pragma unroll
            for (int i = 0; i < 2; ++i) {
                const int e = tid + i * NTHREADS;
                const int r = e >> 3, seg = e & 7;
                const float4 v = aregs[ch * 2 + i];
                __half2 h0 = __floats2half2_rn(v.x, v.y);
                __half2 h1 = __floats2half2_rn(v.z, v.w);
                *(uint2*)(As + r * A_PITCH + ch * 32 + seg * 4) =
                    make_uint2(*(uint32_t*)&h0, *(uint32_t*)&h1);
            }
    };

    // --- prologue: B (80KB) via cp.async, A(tile0), tables ---
    {
        const __half2* srcB = d_Bfrag + (size_t)br * 20480;
        #pragma unroll
        for (int i = 0; i < 10; ++i) {
            const int e = tid + i * NTHREADS;         // 0..5119 16B segs
            CP_ASYNC16(sb + OFF_B + e * 16, srcB + e * 4);
        }
        CP_COMMIT();
    }
    ldgA(t0 * TILE_M);
    stsA(A0);
    #pragma unroll
    for (int i = 0; i < 2; ++i) W2s[tid + i * NTHREADS] = W2[tid + i * NTHREADS];
    b1s[tid & 255] = b1[tid & 255];
    Ms[tid & 255]  = d_M[br][tid & 255];
    if (tid < 4) b2s[tid] = b2[tid];
    if (tid == 0) { pp[0] = pw[0]; pp[1] = pb[0]; }
    CP_WAIT0();
    __syncthreads();

    const char* Bs = smem + OFF_B;

    for (int it = 0; it < cnt; ++it) {
        const int rowbase = (t0 + it) * TILE_M;
        const __half* As = (it & 1) ? A1 : A0;

        float acc[2][8][4];
        #pragma unroll
        for (int mt = 0; mt < 2; ++mt)
            #pragma unroll
            for (int nt = 0; nt < 8; ++nt)
                #pragma unroll
                for (int i = 0; i < 4; ++i) acc[mt][nt][i] = 0.f;

        // ---- barrier-free MMA loop: 10 ksteps of 16 ----
        #pragma unroll
        for (int ks = 0; ks < 10; ++ks) {
            uint32_t a[2][4];
            #pragma unroll
            for (int mt = 0; mt < 2; ++mt) {
                const __half* ap = As + (mw * 32 + mt * 16 + gid) * A_PITCH
                                 + ks * 16 + tig * 2;
                a[mt][0] = *(const uint32_t*)(ap);
                a[mt][2] = *(const uint32_t*)(ap + 8);
                a[mt][1] = *(const uint32_t*)(ap + 8 * A_PITCH);
                a[mt][3] = *(const uint32_t*)(ap + 8 * A_PITCH + 8);
            }
            #pragma unroll
            for (int nt = 0; nt < 8; ++nt) {
                const uint2 bv = *(const uint2*)(Bs
                    + (((ks * 32 + nw * 8 + nt) * 32 + lane) * 8));
                #pragma unroll
                for (int mt = 0; mt < 2; ++mt)
                    mma_f16(acc[mt][nt], a[mt], bv.x, bv.y);
            }
        }

        // ---- epilogue part 1: fold acc -> qp (acc dies here) ----
        float qp[4][4];
        #pragma unroll
        for (int r = 0; r < 4; ++r)
            #pragma unroll
            for (int q = 0; q < 4; ++q) qp[r][q] = 0.f;

        #pragma unroll
        for (int nt = 0; nt < 8; ++nt) {
            const int c0 = nw * 64 + nt * 8 + tig * 2;
            const float bb0 = b1s[c0], bb1 = b1s[c0 + 1];
            #pragma unroll
            for (int q = 0; q < 4; ++q) {
                const float w20 = W2s[q * 256 + c0];
                const float w21 = W2s[q * 256 + c0 + 1];
                #pragma unroll
                for (int mt = 0; mt < 2; ++mt) {
                    const float h00 = fmaxf(acc[mt][nt][0] + bb0, 0.f);
                    const float h01 = fmaxf(acc[mt][nt][1] + bb1, 0.f);
                    const float h10 = fmaxf(acc[mt][nt][2] + bb0, 0.f);
                    const float h11 = fmaxf(acc[mt][nt][3] + bb1, 0.f);
                    qp[mt * 2][q]     = fmaf(h00, w20, fmaf(h01, w21, qp[mt * 2][q]));
                    qp[mt * 2 + 1][q] = fmaf(h10, w20, fmaf(h11, w21, qp[mt * 2 + 1][q]));
                }
            }
        }

        // prefetch next tile's A (LDG latency hides under epilogue part 2)
        const int nrb = (it + 1 < cnt) ? (t0 + it + 1) * TILE_M : rowbase;
        ldgA(nrb);

        // ---- epilogue part 2 ----
        #pragma unroll
        for (int r = 0; r < 4; ++r)
            #pragma unroll
            for (int q = 0; q < 4; ++q) {
                float v = qp[r][q];
                v += __shfl_xor_sync(0xffffffffu, v, 1);
                v += __shfl_xor_sync(0xffffffffu, v, 2);
                if (tig == 0) {
                    const int mt = r >> 1, hf = r & 1;
                    const int row = mw * 32 + mt * 16 + hf * 8 + gid;
                    qpart[(nw * 128 + row) * 4 + q] = v;
                }
            }
        __syncthreads();
        {
            const int row = tid >> 2, q = tid & 3;
            float s = 0.f;
            #pragma unroll
            for (int ww = 0; ww < 4; ++ww) s += qpart[(ww * 128 + row) * 4 + q];
            qin[tid] = s + b2s[q];
        }
        __syncthreads();

        if (tid < TILE_M) {
            float cs[4][2];
            #pragma unroll
            for (int i = 0; i < 4; ++i)
                sincosf(0.5f * qin[tid * 4 + i], &cs[i][1], &cs[i][0]);
            float v[16];
            #pragma unroll
            for (int idx = 0; idx < 16; ++idx)
                v[idx] = cs[0][(idx >> 3) & 1] * cs[1][(idx >> 2) & 1]
                       * cs[2][(idx >> 1) & 1] * cs[3][idx & 1];
            float qo = 0.f;
            #pragma unroll
            for (int i = 0; i < 16; ++i) {
                float mv = 0.f;
                #pragma unroll
                for (int j = 0; j < 16; ++j)
                    mv = fmaf(Ms[i * 16 + j], v[j], mv);
                qo = fmaf(v[i], mv, qo);
            }
            out[br * B_TOTAL + rowbase + tid] = fmaf(qo, pp[0], pp[1]);
        }

        // store next tile's A into the alternate buffer; barrier publishes it
        stsA((it & 1) ? A0 : A1);
        __syncthreads();
    }
}

extern "C" void kernel_launch(void* const* d_in, const int* in_sizes, int n_in,
                              void* d_out, int out_size) {
    const float* state  = (const float*)d_in[0];
    const float* action = (const float*)d_in[1];
    const float* q1_W1  = (const float*)d_in[2];
    const float* q1_b1  = (const float*)d_in[3];
    const float* q1_W2  = (const float*)d_in[4];
    const float* q1_b2  = (const float*)d_in[5];
    const float* q2_W1  = (const float*)d_in[6];
    const float* q2_b1  = (const float*)d_in[7];
    const float* q2_W2  = (const float*)d_in[8];
    const float* q2_b2  = (const float*)d_in[9];
    const float* q1_qw  = (const float*)d_in[10];
    const float* q2_qw  = (const float*)d_in[11];
    const float* q1_pw  = (const float*)d_in[12];
    const float* q1_pb  = (const float*)d_in[13];
    const float* q2_pw  = (const float*)d_in[14];
    const float* q2_pb  = (const float*)d_in[15];
    float* out = (float*)d_out;

    int dev = 0, nsm = 148;
    cudaGetDevice(&dev);
    cudaDeviceGetAttribute(&nsm, cudaDevAttrMultiProcessorCount, dev);
    nsm &= ~1;                       // even split across branches
    if (nsm < 2) nsm = 2;

    cudaFuncSetAttribute(critic_mma, cudaFuncAttributeMaxDynamicSharedMemorySize,
                         SMEM_BYTES);

    setup_kernel<<<82, 256>>>(q1_qw, q2_qw, q1_W1, q2_W1);
    critic_mma<<<nsm, NTHREADS, SMEM_BYTES>>>(
        state, action,
        q1_b1, q1_W2, q1_b2,
        q2_b1, q2_W2, q2_b2,
        q1_pw, q1_pb, q2_pw, q2_pb,
        out);
}

// round 7
// speedup vs baseline: 11.2677x; 1.0260x over previous
#include <cuda_runtime.h>
#include <cuda_fp16.h>
#include <math.h>
#include <cstdint>

#define B_TOTAL 131072
#define SD 128
#define AD 32
#define TILE_M 128
#define NTILES 1024            // per branch
#define NTHREADS 512

__device__ float d_M[2][256];
// fp16 B fragments GEMM1: [br][ks(10)][ntile(32)][lane(32)][2 regs] as half2
__device__ __half2 d_Bfrag[2 * 10 * 32 * 32 * 2];
// fp16 B fragments GEMM2 (W2^T, n=8 padded): [br][ks(16)][lane(32)][2] half2
__device__ __half2 d_W2frag[2 * 16 * 32 * 2];

// ---- smem layout (byte offsets) ----
#define OFF_B     0            // 81920B: full W1 frags
#define OFF_A0    81920        // [128][168] halfs = 43008B
#define OFF_A1    124928
#define OFF_W2F   167936       // 4096B
#define OFF_B1S   172032       // 256 floats
#define OFF_MS    173056       // 16x17 floats (padded) = 1088 -> reserve 1152
#define OFF_QPART 174208       // [4][128][4] floats = 8192
#define OFF_B2S   182400
#define OFF_PP    182416
#define SMEM_BYTES 182432

#define A_PITCH 168            // halfs per row (160 data + 8 pad)
#define A_PITCH_B 336          // bytes

__device__ __forceinline__ uint32_t smem_u32(const void* p) {
    uint32_t a;
    asm("{ .reg .u64 t; cvta.to.shared.u64 t, %1; cvt.u32.u64 %0, t; }" : "=r"(a) : "l"(p));
    return a;
}
#define CP_ASYNC16(dst, src) \
    asm volatile("cp.async.cg.shared.global [%0], [%1], 16;" :: "r"(dst), "l"(src) : "memory")
#define CP_COMMIT() asm volatile("cp.async.commit_group;" ::: "memory")
#define CP_WAIT0()  asm volatile("cp.async.wait_group 0;" ::: "memory")

#define LDSM_X4(r0, r1, r2, r3, addr) \
    asm volatile("ldmatrix.sync.aligned.m8n8.x4.shared.b16 {%0,%1,%2,%3}, [%4];" \
        : "=r"(r0), "=r"(r1), "=r"(r2), "=r"(r3) : "r"(addr))

__device__ __forceinline__ void mma_f16(float* d, const uint32_t* a,
                                        uint32_t b0, uint32_t b1) {
    asm volatile(
        "mma.sync.aligned.m16n8k16.row.col.f32.f16.f16.f32 "
        "{%0,%1,%2,%3}, {%4,%5,%6,%7}, {%8,%9}, {%0,%1,%2,%3};"
        : "+f"(d[0]), "+f"(d[1]), "+f"(d[2]), "+f"(d[3])
        : "r"(a[0]), "r"(a[1]), "r"(a[2]), "r"(a[3]), "r"(b0), "r"(b1));
}
__device__ __forceinline__ uint32_t h2u(__half2 h) { return *(uint32_t*)&h; }

// ---------------------------------------------------------------------------
// Setup: blocks 0,1 -> M (256-thread parallel circuit); 2..81 -> W1 frags;
// block 82 -> W2 frags.
// ---------------------------------------------------------------------------
__global__ void setup_kernel(const float* __restrict__ qw1,
                             const float* __restrict__ qw2,
                             const float* __restrict__ W1a,
                             const float* __restrict__ W1b,
                             const float* __restrict__ W2a,
                             const float* __restrict__ W2b) {
    if (blockIdx.x < 2) {
        const int br = blockIdx.x;
        const int t  = threadIdx.x;
        const int j  = t >> 4;
        const int m  = t & 15;
        const float* qw = br ? qw2 : qw1;
        __shared__ float Ur[16][17];
        __shared__ float Ui[16][17];

        float sr = (m == j) ? 1.f : 0.f;
        float si = 0.f;

        for (int l = 0; l < 2; ++l) {
            #pragma unroll
            for (int i = 0; i < 4; ++i) {
                const int st = 8 >> i;
                float cc, ss, pr, pi;
                sincosf(0.5f * qw[(l * 4 + i) * 3 + 0], &ss, &cc);   // RX
                pr = __shfl_xor_sync(0xffffffffu, sr, st);
                pi = __shfl_xor_sync(0xffffffffu, si, st);
                { float nr = cc * sr + ss * pi, ni = cc * si - ss * pr;
                  sr = nr; si = ni; }
                sincosf(0.5f * qw[(l * 4 + i) * 3 + 1], &ss, &cc);   // RY
                pr = __shfl_xor_sync(0xffffffffu, sr, st);
                pi = __shfl_xor_sync(0xffffffffu, si, st);
                { const float e = (m & st) ? ss : -ss;
                  float nr = cc * sr + e * pr, ni = cc * si + e * pi;
                  sr = nr; si = ni; }
                sincosf(0.5f * qw[(l * 4 + i) * 3 + 2], &ss, &cc);   // RZ
                { const float e = (m & st) ? -ss : ss;
                  float nr = cc * sr + e * si, ni = cc * si - e * sr;
                  sr = nr; si = ni; }
            }
            #pragma unroll
            for (int e = 0; e < 4; ++e) {
                const int sc  = 8 >> e;
                const int stt = 8 >> ((e + 1) & 3);
                const float pr = __shfl_xor_sync(0xffffffffu, sr, stt);
                const float pi = __shfl_xor_sync(0xffffffffu, si, stt);
                if (m & sc) { sr = pr; si = pi; }
            }
        }
        Ur[m][j] = sr;
        Ui[m][j] = si;
        __syncthreads();
        {
            const int i = t >> 4, jj = t & 15;
            float acc = 0.f;
            #pragma unroll
            for (int k = 0; k < 16; ++k) {
                const float d = (k < 8) ? 1.f : -1.f;
                acc += d * (Ur[k][i] * Ur[k][jj] + Ui[k][i] * Ui[k][jj]);
            }
            d_M[br][i * 16 + jj] = acc;
        }
    } else if (blockIdx.x < 82) {
        const int idx = (blockIdx.x - 2) * 256 + threadIdx.x;
        const int lane  = idx & 31;
        const int ntile = (idx >> 5) & 31;
        const int t     = idx >> 10;       // br*10 + ks
        const int ks    = t % 10;
        const int br    = t / 10;
        const float* W1 = br ? W1b : W1a;
        const int n  = ntile * 8 + (lane >> 2);
        const int k0 = ks * 16 + (lane & 3) * 2;
        d_Bfrag[idx * 2]     = __floats2half2_rn(W1[n * 160 + k0],     W1[n * 160 + k0 + 1]);
        d_Bfrag[idx * 2 + 1] = __floats2half2_rn(W1[n * 160 + k0 + 8], W1[n * 160 + k0 + 9]);
    } else {
        // W2 fragments: 1024 entries, 256 threads x 4
        #pragma unroll
        for (int rep = 0; rep < 4; ++rep) {
            const int idx = threadIdx.x + rep * 256;   // 0..1023
            const int br   = idx >> 9;
            const int rem  = idx & 511;
            const int ks   = rem >> 5;
            const int lane = rem & 31;
            const float* W2 = br ? W2b : W2a;
            const int n  = lane >> 2;
            const int k0 = ks * 16 + (lane & 3) * 2;
            __half2 v0 = __floats2half2_rn(0.f, 0.f), v1 = v0;
            if (n < 4) {
                v0 = __floats2half2_rn(W2[n * 256 + k0],     W2[n * 256 + k0 + 1]);
                v1 = __floats2half2_rn(W2[n * 256 + k0 + 8], W2[n * 256 + k0 + 9]);
            }
            d_W2frag[idx * 2]     = v0;
            d_W2frag[idx * 2 + 1] = v1;
        }
    }
}

// ---------------------------------------------------------------------------
// Persistent fused critic. GEMM1 + GEMM2 both on tensor pipe; fused
// reduce+quantum across all 512 threads.
// ---------------------------------------------------------------------------
__global__ __launch_bounds__(NTHREADS, 1)
void critic_mma(const float* __restrict__ state,
                const float* __restrict__ action,
                const float* __restrict__ b1a, const float* __restrict__ b2a,
                const float* __restrict__ b1b, const float* __restrict__ b2b,
                const float* __restrict__ pwa, const float* __restrict__ pba,
                const float* __restrict__ pwb, const float* __restrict__ pbb,
                float* __restrict__ out) {
    extern __shared__ char smem[];
    const uint32_t sb = smem_u32(smem);
    const int tid  = threadIdx.x;
    const int w    = tid >> 5;
    const int lane = tid & 31;
    const int mw   = w >> 2;
    const int nw   = w & 3;
    const int gid  = lane >> 2;
    const int tig  = lane & 3;

    const int br   = blockIdx.x & 1;
    const int cid  = blockIdx.x >> 1;
    const int ncta = gridDim.x >> 1;
    const int per  = NTILES / ncta;
    const int rem  = NTILES % ncta;
    const int t0   = cid * per + (cid < rem ? cid : rem);
    const int cnt  = per + (cid < rem ? 1 : 0);

    const float* b1 = br ? b1b : b1a;
    const float* b2 = br ? b2b : b2a;
    const float* pw = br ? pwb : pwa;
    const float* pb = br ? pbb : pba;

    float* b1s   = (float*)(smem + OFF_B1S);
    float* Ms    = (float*)(smem + OFF_MS);      // pitch 17
    float* qpart = (float*)(smem + OFF_QPART);
    float* b2s   = (float*)(smem + OFF_B2S);
    float* pp    = (float*)(smem + OFF_PP);
    __half* A0   = (__half*)(smem + OFF_A0);
    __half* A1   = (__half*)(smem + OFF_A1);

    // --- A staging ---
    float4 aregs[10];
    auto ldgA = [&](int rowbase) {
        #pragma unroll
        for (int ch = 0; ch < 5; ++ch)
            #pragma unroll
            for (int i = 0; i < 2; ++i) {
                const int e = tid + i * NTHREADS;
                const int r = e >> 3, seg = e & 7;
                const float* src = (ch < 4)
                    ? state  + (size_t)(rowbase + r) * SD + ch * 32 + seg * 4
                    : action + (size_t)(rowbase + r) * AD + seg * 4;
                aregs[ch * 2 + i] = *(const float4*)src;
            }
    };
    auto stsA = [&](__half* As) {
        #pragma unroll
        for (int ch = 0; ch < 5; ++ch)
            #pragma unroll
            for (int i = 0; i < 2; ++i) {
                const int e = tid + i * NTHREADS;
                const int r = e >> 3, seg = e & 7;
                const float4 v = aregs[ch * 2 + i];
                __half2 h0 = __floats2half2_rn(v.x, v.y);
                __half2 h1 = __floats2half2_rn(v.z, v.w);
                *(uint2*)(As + r * A_PITCH + ch * 32 + seg * 4) =
                    make_uint2(h2u(h0), h2u(h1));
            }
    };

    // --- prologue ---
    {
        const __half2* srcB = d_Bfrag + (size_t)br * 20480;
        #pragma unroll
        for (int i = 0; i < 10; ++i) {
            const int e = tid + i * NTHREADS;
            CP_ASYNC16(sb + OFF_B + e * 16, srcB + e * 4);
        }
        if (tid < 256)
            CP_ASYNC16(sb + OFF_W2F + tid * 16, d_W2frag + br * 1024 + tid * 4);
        CP_COMMIT();
    }
    ldgA(t0 * TILE_M);
    stsA(A0);
    if (tid < 256) {
        b1s[tid] = b1[tid];
        Ms[(tid >> 4) * 17 + (tid & 15)] = d_M[br][tid];
    }
    if (tid < 4) b2s[tid] = b2[tid];
    if (tid == 0) { pp[0] = pw[0]; pp[1] = pb[0]; }
    CP_WAIT0();
    __syncthreads();

    const char* Bs   = smem + OFF_B;
    const char* W2Fs = smem + OFF_W2F;

    // ldmatrix per-lane address pieces
    const uint32_t lrow  = (lane & 7) + (((lane >> 3) & 1) << 3);
    const uint32_t lkofs = (lane >> 4) * 16;   // bytes

    for (int it = 0; it < cnt; ++it) {
        const int rowbase = (t0 + it) * TILE_M;
        const uint32_t Ab = sb + ((it & 1) ? OFF_A1 : OFF_A0)
                          + (mw * 32 + lrow) * A_PITCH_B + lkofs;

        float acc[2][8][4];
        #pragma unroll
        for (int mt = 0; mt < 2; ++mt)
            #pragma unroll
            for (int nt = 0; nt < 8; ++nt)
                #pragma unroll
                for (int i = 0; i < 4; ++i) acc[mt][nt][i] = 0.f;

        // ---- GEMM1: 10 ksteps, barrier-free ----
        #pragma unroll
        for (int ks = 0; ks < 10; ++ks) {
            uint32_t a[2][4];
            #pragma unroll
            for (int mt = 0; mt < 2; ++mt)
                LDSM_X4(a[mt][0], a[mt][1], a[mt][2], a[mt][3],
                        Ab + mt * 16 * A_PITCH_B + ks * 32);
            #pragma unroll
            for (int nt = 0; nt < 8; ++nt) {
                const uint2 bv = *(const uint2*)(Bs
                    + (((ks * 32 + nw * 8 + nt) * 32 + lane) * 8));
                #pragma unroll
                for (int mt = 0; mt < 2; ++mt)
                    mma_f16(acc[mt][nt], a[mt], bv.x, bv.y);
            }
        }

        // ---- GEMM2 on tensor pipe: h = relu(acc + b1) in fp16 ----
        float acc2[2][4];
        #pragma unroll
        for (int mt = 0; mt < 2; ++mt)
            #pragma unroll
            for (int i = 0; i < 4; ++i) acc2[mt][i] = 0.f;

        #pragma unroll
        for (int ks2 = 0; ks2 < 4; ++ks2) {
            const int c0 = nw * 64 + ks2 * 16 + tig * 2;
            const float bb0 = b1s[c0],     bb1 = b1s[c0 + 1];
            const float bb2 = b1s[c0 + 8], bb3 = b1s[c0 + 9];
            const uint2 bv = *(const uint2*)(W2Fs + ((nw * 4 + ks2) * 32 + lane) * 8);
            #pragma unroll
            for (int mt = 0; mt < 2; ++mt) {
                const float* p0 = acc[mt][2 * ks2];
                const float* p1 = acc[mt][2 * ks2 + 1];
                uint32_t af[4];
                af[0] = h2u(__floats2half2_rn(fmaxf(p0[0] + bb0, 0.f),
                                              fmaxf(p0[1] + bb1, 0.f)));
                af[1] = h2u(__floats2half2_rn(fmaxf(p0[2] + bb0, 0.f),
                                              fmaxf(p0[3] + bb1, 0.f)));
                af[2] = h2u(__floats2half2_rn(fmaxf(p1[0] + bb2, 0.f),
                                              fmaxf(p1[1] + bb3, 0.f)));
                af[3] = h2u(__floats2half2_rn(fmaxf(p1[2] + bb2, 0.f),
                                              fmaxf(p1[3] + bb3, 0.f)));
                mma_f16(acc2[mt], af, bv.x, bv.y);
            }
        }

        // prefetch next tile's A (latency hides under stores + barrier + reduce)
        ldgA((it + 1 < cnt) ? (t0 + it + 1) * TILE_M : rowbase);

        // qpart stores: thread holds (row, n) for n = tig*2, tig*2+1 (tig<2)
        if (tig < 2) {
            #pragma unroll
            for (int mt = 0; mt < 2; ++mt) {
                const int row0 = mw * 32 + mt * 16 + gid;
                qpart[(nw * 128 + row0) * 4 + tig * 2]     = acc2[mt][0];
                qpart[(nw * 128 + row0) * 4 + tig * 2 + 1] = acc2[mt][1];
                qpart[(nw * 128 + row0 + 8) * 4 + tig * 2]     = acc2[mt][2];
                qpart[(nw * 128 + row0 + 8) * 4 + tig * 2 + 1] = acc2[mt][3];
            }
        }
        __syncthreads();

        // store next tile's A into alternate buffer (published by end barrier)
        stsA((it & 1) ? A0 : A1);

        // ---- fused reduce + quantum: 4 threads per row ----
        {
            const int row = tid >> 2, q = tid & 3;
            float s = 0.f;
            #pragma unroll
            for (int ww = 0; ww < 4; ++ww) s += qpart[(ww * 128 + row) * 4 + q];
            const float qin = s + b2s[q];

            float cc, ssn;
            sincosf(0.5f * qin, &ssn, &cc);
            float csc[4], css[4];
            #pragma unroll
            for (int k = 0; k < 4; ++k) {
                csc[k] = __shfl_xor_sync(0xffffffffu, cc,  q ^ k);
                css[k] = __shfl_xor_sync(0xffffffffu, ssn, q ^ k);
            }
            float v[16];
            #pragma unroll
            for (int idx = 0; idx < 16; ++idx)
                v[idx] = ((idx & 8) ? css[0] : csc[0])
                       * ((idx & 4) ? css[1] : csc[1])
                       * ((idx & 2) ? css[2] : csc[2])
                       * ((idx & 1) ? css[3] : csc[3]);
            float qo = 0.f;
            #pragma unroll
            for (int ii = 0; ii < 4; ++ii) {
                const int i = q * 4 + ii;
                float mv = 0.f;
                #pragma unroll
                for (int j = 0; j < 16; ++j)
                    mv = fmaf(Ms[i * 17 + j], v[j], mv);
                qo = fmaf(v[i], mv, qo);
            }
            qo += __shfl_xor_sync(0xffffffffu, qo, 1);
            qo += __shfl_xor_sync(0xffffffffu, qo, 2);
            if (q == 0)
                out[br * B_TOTAL + rowbase + row] = fmaf(qo, pp[0], pp[1]);
        }
        __syncthreads();
    }
}

extern "C" void kernel_launch(void* const* d_in, const int* in_sizes, int n_in,
                              void* d_out, int out_size) {
    const float* state  = (const float*)d_in[0];
    const float* action = (const float*)d_in[1];
    const float* q1_W1  = (const float*)d_in[2];
    const float* q1_b1  = (const float*)d_in[3];
    const float* q1_W2  = (const float*)d_in[4];
    const float* q1_b2  = (const float*)d_in[5];
    const float* q2_W1  = (const float*)d_in[6];
    const float* q2_b1  = (const float*)d_in[7];
    const float* q2_W2  = (const float*)d_in[8];
    const float* q2_b2  = (const float*)d_in[9];
    const float* q1_qw  = (const float*)d_in[10];
    const float* q2_qw  = (const float*)d_in[11];
    const float* q1_pw  = (const float*)d_in[12];
    const float* q1_pb  = (const float*)d_in[13];
    const float* q2_pw  = (const float*)d_in[14];
    const float* q2_pb  = (const float*)d_in[15];
    float* out = (float*)d_out;

    int dev = 0, nsm = 148;
    cudaGetDevice(&dev);
    cudaDeviceGetAttribute(&nsm, cudaDevAttrMultiProcessorCount, dev);
    nsm &= ~1;
    if (nsm < 2) nsm = 2;

    cudaFuncSetAttribute(critic_mma, cudaFuncAttributeMaxDynamicSharedMemorySize,
                         SMEM_BYTES);

    setup_kernel<<<83, 256>>>(q1_qw, q2_qw, q1_W1, q2_W1, q1_W2, q2_W2);
    critic_mma<<<nsm, NTHREADS, SMEM_BYTES>>>(
        state, action,
        q1_b1, q1_b2,
        q2_b1, q2_b2,
        q1_pw, q1_pb, q2_pw, q2_pb,
        out);
}

// round 8
// speedup vs baseline: 12.0709x; 1.0713x over previous
#include <cuda_runtime.h>
#include <cuda_fp16.h>
#include <math.h>
#include <cstdint>

#define B_TOTAL 131072
#define SD 128
#define AD 32
#define TILE_M 64
#define NTILES 2048            // per branch
#define NTHREADS 256

__device__ float d_M[2][256];
// fp16 B fragments GEMM1: [br][ks(10)][ntile(32)][lane(32)][2 regs] as half2
__device__ __half2 d_Bfrag[2 * 10 * 32 * 32 * 2];
// fp16 B fragments GEMM2 (W2^T, n=8 padded): [br][ks(16)][lane(32)][2] half2
__device__ __half2 d_W2frag[2 * 16 * 32 * 2];

// ---- smem layout (byte offsets), per CTA ----
#define OFF_B     0            // 81920B: full W1 frags
#define OFF_A     81920        // [64][168] halfs = 21504B (single buffer)
#define OFF_W2F   103424       // 4096B
#define OFF_B1S   107520       // 256 floats = 1024B
#define OFF_MS    108544       // 16x17 floats -> 1152B reserved
#define OFF_QPART 109696       // [4][64][4] floats = 4096B
#define OFF_B2S   113792       // 16B
#define OFF_PP    113808       // 8B
#define SMEM_BYTES 113824      // x2 CTAs = 227648 <= 228KB

#define A_PITCH 168            // halfs per row (160 data + 8 pad)
#define A_PITCH_B 336          // bytes

__device__ __forceinline__ uint32_t smem_u32(const void* p) {
    uint32_t a;
    asm("{ .reg .u64 t; cvta.to.shared.u64 t, %1; cvt.u32.u64 %0, t; }" : "=r"(a) : "l"(p));
    return a;
}
#define CP_ASYNC16(dst, src) \
    asm volatile("cp.async.cg.shared.global [%0], [%1], 16;" :: "r"(dst), "l"(src) : "memory")
#define CP_COMMIT() asm volatile("cp.async.commit_group;" ::: "memory")
#define CP_WAIT0()  asm volatile("cp.async.wait_group 0;" ::: "memory")

#define LDSM_X4(r0, r1, r2, r3, addr) \
    asm volatile("ldmatrix.sync.aligned.m8n8.x4.shared.b16 {%0,%1,%2,%3}, [%4];" \
        : "=r"(r0), "=r"(r1), "=r"(r2), "=r"(r3) : "r"(addr))

__device__ __forceinline__ void mma_f16(float* d, const uint32_t* a,
                                        uint32_t b0, uint32_t b1) {
    asm volatile(
        "mma.sync.aligned.m16n8k16.row.col.f32.f16.f16.f32 "
        "{%0,%1,%2,%3}, {%4,%5,%6,%7}, {%8,%9}, {%0,%1,%2,%3};"
        : "+f"(d[0]), "+f"(d[1]), "+f"(d[2]), "+f"(d[3])
        : "r"(a[0]), "r"(a[1]), "r"(a[2]), "r"(a[3]), "r"(b0), "r"(b1));
}
__device__ __forceinline__ uint32_t h2u(__half2 h) { return *(uint32_t*)&h; }

// ---------------------------------------------------------------------------
// Setup: blocks 0,1 -> M (256-thread parallel circuit); 2..81 -> W1 frags;
// block 82 -> W2 frags.
// ---------------------------------------------------------------------------
__global__ void setup_kernel(const float* __restrict__ qw1,
                             const float* __restrict__ qw2,
                             const float* __restrict__ W1a,
                             const float* __restrict__ W1b,
                             const float* __restrict__ W2a,
                             const float* __restrict__ W2b) {
    if (blockIdx.x < 2) {
        const int br = blockIdx.x;
        const int t  = threadIdx.x;
        const int j  = t >> 4;
        const int m  = t & 15;
        const float* qw = br ? qw2 : qw1;
        __shared__ float Ur[16][17];
        __shared__ float Ui[16][17];

        float sr = (m == j) ? 1.f : 0.f;
        float si = 0.f;

        for (int l = 0; l < 2; ++l) {
            #pragma unroll
            for (int i = 0; i < 4; ++i) {
                const int st = 8 >> i;
                float cc, ss, pr, pi;
                sincosf(0.5f * qw[(l * 4 + i) * 3 + 0], &ss, &cc);   // RX
                pr = __shfl_xor_sync(0xffffffffu, sr, st);
                pi = __shfl_xor_sync(0xffffffffu, si, st);
                { float nr = cc * sr + ss * pi, ni = cc * si - ss * pr;
                  sr = nr; si = ni; }
                sincosf(0.5f * qw[(l * 4 + i) * 3 + 1], &ss, &cc);   // RY
                pr = __shfl_xor_sync(0xffffffffu, sr, st);
                pi = __shfl_xor_sync(0xffffffffu, si, st);
                { const float e = (m & st) ? ss : -ss;
                  float nr = cc * sr + e * pr, ni = cc * si + e * pi;
                  sr = nr; si = ni; }
                sincosf(0.5f * qw[(l * 4 + i) * 3 + 2], &ss, &cc);   // RZ
                { const float e = (m & st) ? -ss : ss;
                  float nr = cc * sr + e * si, ni = cc * si - e * sr;
                  sr = nr; si = ni; }
            }
            #pragma unroll
            for (int e = 0; e < 4; ++e) {
                const int sc  = 8 >> e;
                const int stt = 8 >> ((e + 1) & 3);
                const float pr = __shfl_xor_sync(0xffffffffu, sr, stt);
                const float pi = __shfl_xor_sync(0xffffffffu, si, stt);
                if (m & sc) { sr = pr; si = pi; }
            }
        }
        Ur[m][j] = sr;
        Ui[m][j] = si;
        __syncthreads();
        {
            const int i = t >> 4, jj = t & 15;
            float acc = 0.f;
            #pragma unroll
            for (int k = 0; k < 16; ++k) {
                const float d = (k < 8) ? 1.f : -1.f;
                acc += d * (Ur[k][i] * Ur[k][jj] + Ui[k][i] * Ui[k][jj]);
            }
            d_M[br][i * 16 + jj] = acc;
        }
    } else if (blockIdx.x < 82) {
        const int idx = (blockIdx.x - 2) * 256 + threadIdx.x;
        const int lane  = idx & 31;
        const int ntile = (idx >> 5) & 31;
        const int t     = idx >> 10;       // br*10 + ks
        const int ks    = t % 10;
        const int br    = t / 10;
        const float* W1 = br ? W1b : W1a;
        const int n  = ntile * 8 + (lane >> 2);
        const int k0 = ks * 16 + (lane & 3) * 2;
        d_Bfrag[idx * 2]     = __floats2half2_rn(W1[n * 160 + k0],     W1[n * 160 + k0 + 1]);
        d_Bfrag[idx * 2 + 1] = __floats2half2_rn(W1[n * 160 + k0 + 8], W1[n * 160 + k0 + 9]);
    } else {
        #pragma unroll
        for (int rep = 0; rep < 4; ++rep) {
            const int idx = threadIdx.x + rep * 256;   // 0..1023
            const int br   = idx >> 9;
            const int rem  = idx & 511;
            const int ks   = rem >> 5;
            const int lane = rem & 31;
            const float* W2 = br ? W2b : W2a;
            const int n  = lane >> 2;
            const int k0 = ks * 16 + (lane & 3) * 2;
            __half2 v0 = __floats2half2_rn(0.f, 0.f), v1 = v0;
            if (n < 4) {
                v0 = __floats2half2_rn(W2[n * 256 + k0],     W2[n * 256 + k0 + 1]);
                v1 = __floats2half2_rn(W2[n * 256 + k0 + 8], W2[n * 256 + k0 + 9]);
            }
            d_W2frag[idx * 2]     = v0;
            d_W2frag[idx * 2 + 1] = v1;
        }
    }
}

// ---------------------------------------------------------------------------
// Persistent fused critic, 2 CTAs/SM. Each CTA: 64-row tiles, 8 warps
// (2 row-warps x 4 col-warps). Single A buffer; the co-resident CTA hides
// the serial epilogue/staging region.
// ---------------------------------------------------------------------------
__global__ __launch_bounds__(NTHREADS, 2)
void critic_mma(const float* __restrict__ state,
                const float* __restrict__ action,
                const float* __restrict__ b1a, const float* __restrict__ b2a,
                const float* __restrict__ b1b, const float* __restrict__ b2b,
                const float* __restrict__ pwa, const float* __restrict__ pba,
                const float* __restrict__ pwb, const float* __restrict__ pbb,
                float* __restrict__ out) {
    extern __shared__ char smem[];
    const uint32_t sb = smem_u32(smem);
    const int tid  = threadIdx.x;
    const int w    = tid >> 5;
    const int lane = tid & 31;
    const int mw   = w >> 2;        // 0..1
    const int nw   = w & 3;         // 0..3
    const int gid  = lane >> 2;
    const int tig  = lane & 3;

    const int br   = blockIdx.x & 1;
    const int cid  = blockIdx.x >> 1;
    const int ncta = gridDim.x >> 1;
    const int per  = NTILES / ncta;
    const int rem  = NTILES % ncta;
    const int t0   = cid * per + (cid < rem ? cid : rem);
    const int cnt  = per + (cid < rem ? 1 : 0);

    const float* b1 = br ? b1b : b1a;
    const float* b2 = br ? b2b : b2a;
    const float* pw = br ? pwb : pwa;
    const float* pb = br ? pbb : pba;

    float* b1s   = (float*)(smem + OFF_B1S);
    float* Ms    = (float*)(smem + OFF_MS);      // pitch 17
    float* qpart = (float*)(smem + OFF_QPART);
    float* b2s   = (float*)(smem + OFF_B2S);
    float* pp    = (float*)(smem + OFF_PP);
    __half* As   = (__half*)(smem + OFF_A);

    // --- A staging: 64 x 160 fp32 -> regs -> fp16 smem ---
    float4 aregs[10];
    auto ldgA = [&](int rowbase) {
        #pragma unroll
        for (int ch = 0; ch < 5; ++ch)
            #pragma unroll
            for (int i = 0; i < 2; ++i) {
                const int e = tid + i * NTHREADS;     // 0..511
                const int r = e >> 3, seg = e & 7;    // 64 rows x 8 segs
                const float* src = (ch < 4)
                    ? state  + (size_t)(rowbase + r) * SD + ch * 32 + seg * 4
                    : action + (size_t)(rowbase + r) * AD + seg * 4;
                aregs[ch * 2 + i] = *(const float4*)src;
            }
    };
    auto stsA = [&]() {
        #pragma unroll
        for (int ch = 0; ch < 5; ++ch)
            #pragma unroll
            for (int i = 0; i < 2; ++i) {
                const int e = tid + i * NTHREADS;
                const int r = e >> 3, seg = e & 7;
                const float4 v = aregs[ch * 2 + i];
                __half2 h0 = __floats2half2_rn(v.x, v.y);
                __half2 h1 = __floats2half2_rn(v.z, v.w);
                *(uint2*)(As + r * A_PITCH + ch * 32 + seg * 4) =
                    make_uint2(h2u(h0), h2u(h1));
            }
    };

    // --- prologue: B frags (80KB), W2 frags, tables, A(tile0) ---
    {
        const __half2* srcB = d_Bfrag + (size_t)br * 20480;
        #pragma unroll
        for (int i = 0; i < 20; ++i) {
            const int e = tid + i * NTHREADS;         // 0..5119 16B segs
            CP_ASYNC16(sb + OFF_B + e * 16, srcB + e * 4);
        }
        CP_ASYNC16(sb + OFF_W2F + tid * 16, d_W2frag + br * 1024 + tid * 4);
        CP_COMMIT();
    }
    ldgA(t0 * TILE_M);
    stsA();
    b1s[tid] = b1[tid];
    Ms[(tid >> 4) * 17 + (tid & 15)] = d_M[br][tid];
    if (tid < 4) b2s[tid] = b2[tid];
    if (tid == 0) { pp[0] = pw[0]; pp[1] = pb[0]; }
    CP_WAIT0();
    __syncthreads();

    const char* Bs   = smem + OFF_B;
    const char* W2Fs = smem + OFF_W2F;

    // ldmatrix per-lane address pieces
    const uint32_t lrow  = (lane & 7) + (((lane >> 3) & 1) << 3);
    const uint32_t lkofs = (lane >> 4) * 16;   // bytes
    const uint32_t Ab0 = sb + OFF_A + (mw * 32 + lrow) * A_PITCH_B + lkofs;

    for (int it = 0; it < cnt; ++it) {
        const int rowbase = (t0 + it) * TILE_M;

        float acc[2][8][4];
        #pragma unroll
        for (int mt = 0; mt < 2; ++mt)
            #pragma unroll
            for (int nt = 0; nt < 8; ++nt)
                #pragma unroll
                for (int i = 0; i < 4; ++i) acc[mt][nt][i] = 0.f;

        // ---- GEMM1: 10 ksteps, barrier-free ----
        #pragma unroll
        for (int ks = 0; ks < 10; ++ks) {
            uint32_t a[2][4];
            #pragma unroll
            for (int mt = 0; mt < 2; ++mt)
                LDSM_X4(a[mt][0], a[mt][1], a[mt][2], a[mt][3],
                        Ab0 + mt * 16 * A_PITCH_B + ks * 32);
            #pragma unroll
            for (int nt = 0; nt < 8; ++nt) {
                const uint2 bv = *(const uint2*)(Bs
                    + (((ks * 32 + nw * 8 + nt) * 32 + lane) * 8));
                #pragma unroll
                for (int mt = 0; mt < 2; ++mt)
                    mma_f16(acc[mt][nt], a[mt], bv.x, bv.y);
            }
        }
        __syncthreads();     // A buffer free; all warps done with this tile's A

        // ---- GEMM2 on tensor pipe: h = relu(acc + b1) in fp16 ----
        float acc2[2][4];
        #pragma unroll
        for (int mt = 0; mt < 2; ++mt)
            #pragma unroll
            for (int i = 0; i < 4; ++i) acc2[mt][i] = 0.f;

        #pragma unroll
        for (int ks2 = 0; ks2 < 4; ++ks2) {
            const int c0 = nw * 64 + ks2 * 16 + tig * 2;
            const float bb0 = b1s[c0],     bb1 = b1s[c0 + 1];
            const float bb2 = b1s[c0 + 8], bb3 = b1s[c0 + 9];
            const uint2 bv = *(const uint2*)(W2Fs + ((nw * 4 + ks2) * 32 + lane) * 8);
            #pragma unroll
            for (int mt = 0; mt < 2; ++mt) {
                const float* p0 = acc[mt][2 * ks2];
                const float* p1 = acc[mt][2 * ks2 + 1];
                uint32_t af[4];
                af[0] = h2u(__floats2half2_rn(fmaxf(p0[0] + bb0, 0.f),
                                              fmaxf(p0[1] + bb1, 0.f)));
                af[1] = h2u(__floats2half2_rn(fmaxf(p0[2] + bb0, 0.f),
                                              fmaxf(p0[3] + bb1, 0.f)));
                af[2] = h2u(__floats2half2_rn(fmaxf(p1[0] + bb2, 0.f),
                                              fmaxf(p1[1] + bb3, 0.f)));
                af[3] = h2u(__floats2half2_rn(fmaxf(p1[2] + bb2, 0.f),
                                              fmaxf(p1[3] + bb3, 0.f)));
                mma_f16(acc2[mt], af, bv.x, bv.y);
            }
        }

        // prefetch next tile's A (latency covered by reduce below)
        ldgA((it + 1 < cnt) ? (t0 + it + 1) * TILE_M : rowbase);

        // qpart stores: thread holds (row, n) for n = tig*2, tig*2+1 (tig<2)
        if (tig < 2) {
            #pragma unroll
            for (int mt = 0; mt < 2; ++mt) {
                const int row0 = mw * 32 + mt * 16 + gid;
                qpart[(nw * 64 + row0) * 4 + tig * 2]     = acc2[mt][0];
                qpart[(nw * 64 + row0) * 4 + tig * 2 + 1] = acc2[mt][1];
                qpart[(nw * 64 + row0 + 8) * 4 + tig * 2]     = acc2[mt][2];
                qpart[(nw * 64 + row0 + 8) * 4 + tig * 2 + 1] = acc2[mt][3];
            }
        }
        __syncthreads();

        // ---- fused reduce + quantum: 4 threads per row (256 = 64x4) ----
        {
            const int row = tid >> 2, q = tid & 3;
            float s = 0.f;
            #pragma unroll
            for (int ww = 0; ww < 4; ++ww) s += qpart[(ww * 64 + row) * 4 + q];
            const float qin = s + b2s[q];

            float cc, ssn;
            sincosf(0.5f * qin, &ssn, &cc);
            float csc[4], css[4];
            #pragma unroll
            for (int k = 0; k < 4; ++k) {
                csc[k] = __shfl_xor_sync(0xffffffffu, cc,  q ^ k);
                css[k] = __shfl_xor_sync(0xffffffffu, ssn, q ^ k);
            }
            float v[16];
            #pragma unroll
            for (int idx = 0; idx < 16; ++idx)
                v[idx] = ((idx & 8) ? css[0] : csc[0])
                       * ((idx & 4) ? css[1] : csc[1])
                       * ((idx & 2) ? css[2] : csc[2])
                       * ((idx & 1) ? css[3] : csc[3]);
            float qo = 0.f;
            #pragma unroll
            for (int ii = 0; ii < 4; ++ii) {
                const int i = q * 4 + ii;
                float mv = 0.f;
                #pragma unroll
                for (int j = 0; j < 16; ++j)
                    mv = fmaf(Ms[i * 17 + j], v[j], mv);
                qo = fmaf(v[i], mv, qo);
            }
            qo += __shfl_xor_sync(0xffffffffu, qo, 1);
            qo += __shfl_xor_sync(0xffffffffu, qo, 2);
            if (q == 0)
                out[br * B_TOTAL + rowbase + row] = fmaf(qo, pp[0], pp[1]);
        }

        // store next tile's A (all reads of old A done at barrier above)
        stsA();
        __syncthreads();
    }
}

extern "C" void kernel_launch(void* const* d_in, const int* in_sizes, int n_in,
                              void* d_out, int out_size) {
    const float* state  = (const float*)d_in[0];
    const float* action = (const float*)d_in[1];
    const float* q1_W1  = (const float*)d_in[2];
    const float* q1_b1  = (const float*)d_in[3];
    const float* q1_W2  = (const float*)d_in[4];
    const float* q1_b2  = (const float*)d_in[5];
    const float* q2_W1  = (const float*)d_in[6];
    const float* q2_b1  = (const float*)d_in[7];
    const float* q2_W2  = (const float*)d_in[8];
    const float* q2_b2  = (const float*)d_in[9];
    const float* q1_qw  = (const float*)d_in[10];
    const float* q2_qw  = (const float*)d_in[11];
    const float* q1_pw  = (const float*)d_in[12];
    const float* q1_pb  = (const float*)d_in[13];
    const float* q2_pw  = (const float*)d_in[14];
    const float* q2_pb  = (const float*)d_in[15];
    float* out = (float*)d_out;

    int dev = 0, nsm = 148;
    cudaGetDevice(&dev);
    cudaDeviceGetAttribute(&nsm, cudaDevAttrMultiProcessorCount, dev);
    if (nsm < 1) nsm = 1;

    cudaFuncSetAttribute(critic_mma, cudaFuncAttributeMaxDynamicSharedMemorySize,
                         SMEM_BYTES);

    setup_kernel<<<83, 256>>>(q1_qw, q2_qw, q1_W1, q2_W1, q1_W2, q2_W2);
    critic_mma<<<2 * nsm, NTHREADS, SMEM_BYTES>>>(
        state, action,
        q1_b1, q1_b2,
        q2_b1, q2_b2,
        q1_pw, q1_pb, q2_pw, q2_pb,
        out);
}